// round 14
// baseline (speedup 1.0000x reference)
#include <cuda_runtime.h>

namespace {

constexpr int HID  = 256;
constexpr int NOBJ = 20;
constexpr int NFD  = 16;
constexpr int NT   = 128;        // threads per block (fat threads: 8 cols each)
constexpr int KT   = 8;          // weight k-tile rows
constexpr int TILE_F = KT * HID; // floats per weight tile (2048)
constexpr int MAXB = 16384;
constexpr int NBUCK = 6;
constexpr unsigned FULL_MASK = 0xFFFFFFFFu;

using u64 = unsigned long long;

__device__ int d_perm[MAXB];
__device__ int d_cta_base[NBUCK + 1];
__device__ int d_slot_base[NBUCK + 1];

// Precomputed pointer-logit fusion: pl_i = h_i·(g@M + v1) + g·v2 + c
__device__ float d_M[HID * HID];
__device__ float d_pkWT[HID * HID];
__device__ float d_v1[HID];
__device__ float d_v2[HID];
__device__ float d_c;

struct Params {
  const float* __restrict__ nf;   const int* __restrict__ nn_c;
  const float* __restrict__ neW;  const float* __restrict__ neb;
  const float* __restrict__ g1W1; const float* __restrict__ g1b1;
  const float* __restrict__ g1W2; const float* __restrict__ g1b2;
  const float* __restrict__ g2W1; const float* __restrict__ g2b1;
  const float* __restrict__ g2W2; const float* __restrict__ g2b2;
  const float* __restrict__ n1g;  const float* __restrict__ n1b;
  const float* __restrict__ n2g;  const float* __restrict__ n2b;
  const float* __restrict__ ohW;  const float* __restrict__ ohb;
  const float* __restrict__ c1W;  const float* __restrict__ c1b;
  const float* __restrict__ c2W;  const float* __restrict__ c2b;
  const float* __restrict__ pqW;  const float* __restrict__ pqb;
  const float* __restrict__ pkW;  const float* __restrict__ pkb;
  float* __restrict__ out;
  int B;
};

__device__ __forceinline__ int bucket_of(int nc) {
  nc = nc > 0 ? nc : 1;
  if (nc <= 4)  return 0;
  if (nc <= 8)  return 1;
  if (nc <= 10) return 2;
  if (nc <= 12) return 3;
  if (nc <= 16) return 4;
  return 5;
}
__device__ __forceinline__ int gg_of(int b) {
  return (b == 0) ? 8 : ((b < 3) ? 4 : 2);
}

// ---------------- f32x2 packed helpers (carrier: u64, register-only) --------
__device__ __forceinline__ u64 ffma2(u64 a, u64 b, u64 c) {
  u64 r;
  asm("fma.rn.f32x2 %0, %1, %2, %3;" : "=l"(r) : "l"(a), "l"(b), "l"(c));
  return r;
}
__device__ __forceinline__ u64 bcast2(float w) {
  u64 r;
  asm("mov.b64 %0, {%1, %1};" : "=l"(r) : "f"(w));
  return r;
}
__device__ __forceinline__ u64 fadd2(u64 a, u64 b) { return ffma2(a, bcast2(1.0f), b); }
__device__ __forceinline__ u64 fmul2(u64 a, u64 b) { return ffma2(a, b, bcast2(0.0f)); }
__device__ __forceinline__ float2 unpack2(u64 v) {
  float2 f;
  asm("mov.b64 {%0, %1}, %2;" : "=f"(f.x), "=f"(f.y) : "l"(v));
  return f;
}

__device__ __forceinline__ void cp_async16(void* smem, const void* gmem) {
  unsigned s = (unsigned)__cvta_generic_to_shared(smem);
  asm volatile("cp.async.cg.shared.global [%0], [%1], 16;\n" ::"r"(s), "l"(gmem));
}
__device__ __forceinline__ void cp_commit() { asm volatile("cp.async.commit_group;\n"); }
__device__ __forceinline__ void cp_wait1()  { asm volatile("cp.async.wait_group 1;\n"); }
__device__ __forceinline__ void cp_wait0()  { asm volatile("cp.async.wait_group 0;\n"); }

__device__ __forceinline__ void load_tile(float* dst, const float* W, int k0, int tid) {
  const float4* src = reinterpret_cast<const float4*>(W + (size_t)k0 * HID);
  float4* d = reinterpret_cast<float4*>(dst);
  #pragma unroll
  for (int r = 0; r < TILE_F / 4 / NT; r++)
    cp_async16(&d[tid + r * NT], &src[tid + r * NT]);
}

// Stream NTILES weight tiles through an NSTAGES-buffer ring; 1 barrier/tile.
template <int NTILES, int NSTAGES, typename F>
__device__ __forceinline__ void stream_tiles(const float* __restrict__ W,
                                             float* wbuf, int tid, F&& consume) {
  if constexpr (NSTAGES == 3) {
    load_tile(wbuf + 0 * TILE_F, W, 0 * KT, tid);
    cp_commit();
    load_tile(wbuf + 1 * TILE_F, W, 1 * KT, tid);
    cp_commit();
    #pragma unroll 1
    for (int tt = 0; tt < NTILES; tt++) {
      cp_wait1();
      __syncthreads();
      if (tt + 2 < NTILES)
        load_tile(wbuf + ((tt + 2) % 3) * TILE_F, W, (tt + 2) * KT, tid);
      cp_commit();
      consume(wbuf + (tt % 3) * TILE_F, tt * KT);
    }
    __syncthreads();
  } else {
    load_tile(wbuf, W, 0, tid);
    cp_commit();
    #pragma unroll 1
    for (int tt = 0; tt < NTILES; tt++) {
      cp_wait0();
      __syncthreads();
      if (tt + 1 < NTILES) {
        load_tile(wbuf + ((tt + 1) & 1) * TILE_F, W, (tt + 1) * KT, tid);
        cp_commit();
      }
      consume(wbuf + (tt & 1) * TILE_F, tt * KT);
    }
    __syncthreads();
  }
}

template <int NPG>
__device__ __forceinline__ void ld_grp(u64* d, const float* p) {
  const u64* q = reinterpret_cast<const u64*>(p);
  #pragma unroll
  for (int i = 0; i + 2 <= NPG; i += 2) {
    ulonglong2 v = *reinterpret_cast<const ulonglong2*>(q + i);
    d[i] = v.x; d[i + 1] = v.y;
  }
  if constexpr (NPG & 1) d[NPG - 1] = q[NPG - 1];
}

template <int NPG, int KSTR_F>
__device__ __forceinline__ void mma_tile(const float* __restrict__ wb,
                                         const float* __restrict__ hsrc,
                                         int c0, u64 (&acc)[8][NPG]) {
  #pragma unroll 4
  for (int kk = 0; kk < KT; kk++) {
    const float4 wa = *reinterpret_cast<const float4*>(wb + kk * HID + c0);
    const float4 wc = *reinterpret_cast<const float4*>(wb + kk * HID + c0 + 4);
    u64 h[NPG];
    ld_grp<NPG>(h, hsrc + kk * KSTR_F);
    u64 w[8];
    w[0] = bcast2(wa.x); w[1] = bcast2(wa.y); w[2] = bcast2(wa.z); w[3] = bcast2(wa.w);
    w[4] = bcast2(wc.x); w[5] = bcast2(wc.y); w[6] = bcast2(wc.z); w[7] = bcast2(wc.w);
    #pragma unroll
    for (int p = 0; p < NPG; p++) {
      #pragma unroll
      for (int c = 0; c < 8; c++)
        acc[c][p] = ffma2(h[p], w[c], acc[c][p]);
    }
  }
}

// GEMV via direct LDG.128 (weights L1/L2-resident; no smem staging, no
// barriers). Wc = W + c0 (column base). acc[sp][c] += vec_sp[k]*W[k][c0+c].
template <int SPG>
__device__ __forceinline__ void gemv_ldg(const float* __restrict__ Wc,
                                         const float* __restrict__ vec0,
                                         float (&acc)[SPG][8]) {
  #pragma unroll 1
  for (int k0 = 0; k0 < HID; k0 += 4) {
    float4 wa[4], wc4[4];
    #pragma unroll
    for (int u = 0; u < 4; u++) {
      wa[u]  = __ldg(reinterpret_cast<const float4*>(Wc + (size_t)(k0 + u) * HID));
      wc4[u] = __ldg(reinterpret_cast<const float4*>(Wc + (size_t)(k0 + u) * HID + 4));
    }
    #pragma unroll
    for (int u = 0; u < 4; u++) {
      #pragma unroll
      for (int sp = 0; sp < SPG; sp++) {
        const float m = vec0[sp * HID + k0 + u];
        acc[sp][0] = fmaf(m, wa[u].x, acc[sp][0]);
        acc[sp][1] = fmaf(m, wa[u].y, acc[sp][1]);
        acc[sp][2] = fmaf(m, wa[u].z, acc[sp][2]);
        acc[sp][3] = fmaf(m, wa[u].w, acc[sp][3]);
        acc[sp][4] = fmaf(m, wc4[u].x, acc[sp][4]);
        acc[sp][5] = fmaf(m, wc4[u].y, acc[sp][5]);
        acc[sp][6] = fmaf(m, wc4[u].z, acc[sp][6]);
        acc[sp][7] = fmaf(m, wc4[u].w, acc[sp][7]);
      }
    }
  }
}

// ------------------------------------------------------------------
// GG samples per CTA (GG in {2,4,8}); 4 row-groups always.
// ROWSG = GG*NR/4 rows per group; SPG = samples per group (GG8 -> 2).
// Virtual row vr = s*NR + i  ->  grp = vr/ROWSG, slot = vr%ROWSG.
// ------------------------------------------------------------------
template <int GG, int NR, int NSTG>
__device__ __forceinline__ void run(const Params& P, float* sm, int sbase,
                                    int send, int tid) {
  constexpr int ROWSG = GG * NR / 4;
  constexpr int SPG = (GG >= 8) ? 2 : 1;
  constexpr int GPS = (GG >= 4) ? 1 : 4 / GG;
  constexpr int NPG = ROWSG / 2;
  constexpr int GSTR_F = (((NPG * 8) + 15) & ~15) / 4;
  constexpr int KSTR_F = 4 * GSTR_F;

  float* hT   = sm;                       // HID * KSTR_F
  float* wbuf = hT + HID * KSTR_F;        // NSTG * TILE_F
  float* msgs = wbuf + NSTG * TILE_F;     // GG * HID
  float* dsm  = msgs + GG * HID;          // GG
  float* nfs  = wbuf;                     // overlay (embed phase only)
  u64*  red   = reinterpret_cast<u64*>(wbuf);  // overlay (between streams)

  const int lane = tid & 31, warp = tid >> 5;
  const int cg = tid >> 2, rg = tid & 3, c0 = cg * 8;
  const int g = (SPG == 2) ? rg * 2 : rg / GPS;
  const int rbase = (SPG == 2) ? 0 : (rg % GPS) * ROWSG;

  int sid[GG]; int ncv[GG]; float invd[GG]; bool wok[GG];
  #pragma unroll
  for (int s = 0; s < GG; s++) {
    const int ss = sbase + s;
    wok[s] = (ss < send);
    sid[s] = wok[s] ? d_perm[ss] : 0;
    int nc = wok[s] ? P.nn_c[sid[s]] : 0;
    ncv[s] = min(max(nc, 0), NOBJ);
    invd[s] = 1.0f / (float)(ncv[s] > 0 ? ncv[s] : 1);
  }
  int ncvA = 0, ncvB = 0; float invdA = 1.f, invdB = 1.f;
  #pragma unroll
  for (int s = 0; s < GG; s++) {
    if (s == g) { ncvA = ncv[s]; invdA = invd[s]; }
    if (SPG == 2 && s == g + 1) { ncvB = ncv[s]; invdB = invd[s]; }
  }

  // node features
  for (int idx = tid; idx < GG * 80; idx += NT) {
    const int s = idx / 80, o = idx % 80;
    reinterpret_cast<float4*>(nfs)[idx] =
        reinterpret_cast<const float4*>(P.nf + (size_t)sid[s] * (NOBJ * NFD))[o];
  }
  __syncthreads();

  // ---------- node embed ----------
  #pragma unroll
  for (int half = 0; half < 2; half++) {
    const int j = tid + half * NT;
    float wv[NFD];
    #pragma unroll
    for (int k = 0; k < NFD; k++) wv[k] = P.neW[k * HID + j];
    const float bias = P.neb[j];
    #pragma unroll
    for (int s = 0; s < GG; s++) {
      float ms = 0.f;
      #pragma unroll
      for (int i = 0; i < NR; i += 2) {
        float a2[2];
        #pragma unroll
        for (int t = 0; t < 2; t++) {
          const float4* rp = reinterpret_cast<const float4*>(nfs + s * 320 + (i + t) * NFD);
          float4 r0 = rp[0], r1 = rp[1], r2 = rp[2], r3 = rp[3];
          float a = bias;
          a = fmaf(r0.x, wv[0], a);  a = fmaf(r0.y, wv[1], a);
          a = fmaf(r0.z, wv[2], a);  a = fmaf(r0.w, wv[3], a);
          a = fmaf(r1.x, wv[4], a);  a = fmaf(r1.y, wv[5], a);
          a = fmaf(r1.z, wv[6], a);  a = fmaf(r1.w, wv[7], a);
          a = fmaf(r2.x, wv[8], a);  a = fmaf(r2.y, wv[9], a);
          a = fmaf(r2.z, wv[10], a); a = fmaf(r2.w, wv[11], a);
          a = fmaf(r3.x, wv[12], a); a = fmaf(r3.y, wv[13], a);
          a = fmaf(r3.z, wv[14], a); a = fmaf(r3.w, wv[15], a);
          a2[t] = a;
          if (i + t < ncv[s]) ms += a;
        }
        const int vr = s * NR + i;
        const int grp = vr / ROWSG, slot = vr % ROWSG;
        *reinterpret_cast<float2*>(hT + (size_t)j * KSTR_F + grp * GSTR_F + slot) =
            make_float2(a2[0], a2[1]);
      }
      msgs[s * HID + j] = ms * invd[s];
    }
  }
  __syncthreads();

  // ---------- two message-passing layers ----------
  #pragma unroll 1
  for (int L = 0; L < 2; L++) {
    const float* W1 = L ? P.g2W1 : P.g1W1;  const float* b1 = L ? P.g2b1 : P.g1b1;
    const float* W2 = L ? P.g2W2 : P.g1W2;  const float* b2 = L ? P.g2b2 : P.g1b2;
    const float* lg = L ? P.n2g  : P.n1g;   const float* lb = L ? P.n2b  : P.n1b;

    // ---- mac = msg @ W1b via direct LDG (no stream, no barriers) ----
    float mac[SPG][8];
    #pragma unroll
    for (int sp = 0; sp < SPG; sp++)
      #pragma unroll
      for (int c = 0; c < 8; c++) mac[sp][c] = 0.f;
    gemv_ldg<SPG>(W1 + (size_t)HID * HID + c0, msgs + g * HID, mac);

    // ---- t = relu(h @ W1a + mac + b1): stream only the h-part (32 tiles) --
    u64 t2[8][NPG];
    #pragma unroll
    for (int c = 0; c < 8; c++)
      #pragma unroll
      for (int p = 0; p < NPG; p++) t2[c][p] = 0ull;
    stream_tiles<HID / KT, NSTG>(W1, wbuf, tid, [&](const float* wb, int k0) {
      mma_tile<NPG, KSTR_F>(wb, hT + (size_t)k0 * KSTR_F + rg * GSTR_F, c0, t2);
    });

    // ---- epilogue 1: acc2 = h_old + b2 (residual pre-add); hT <- relu(t) ----
    u64 acc2[8][NPG];
    {
      const float4 b1a = *reinterpret_cast<const float4*>(b1 + c0);
      const float4 b1c = *reinterpret_cast<const float4*>(b1 + c0 + 4);
      const float4 b2a = *reinterpret_cast<const float4*>(b2 + c0);
      const float4 b2c = *reinterpret_cast<const float4*>(b2 + c0 + 4);
      const float b1v[8] = {b1a.x, b1a.y, b1a.z, b1a.w, b1c.x, b1c.y, b1c.z, b1c.w};
      const float b2v[8] = {b2a.x, b2a.y, b2a.z, b2a.w, b2c.x, b2c.y, b2c.z, b2c.w};
      #pragma unroll
      for (int c = 0; c < 8; c++) {
        float* hcol = hT + (size_t)(c0 + c) * KSTR_F + rg * GSTR_F;
        u64 hold[NPG];
        ld_grp<NPG>(hold, hcol);
        const u64 b2d = bcast2(b2v[c]);
        #pragma unroll
        for (int p = 0; p < NPG; p++) acc2[c][p] = fadd2(hold[p], b2d);
        #pragma unroll
        for (int p = 0; p < NPG; p++) {
          const int sp = (SPG == 2 && p >= NPG / 2) ? 1 : 0;
          const float m = mac[sp][c] + b1v[c];
          float2 u = unpack2(t2[c][p]);
          *reinterpret_cast<float2*>(hcol + 2 * p) =
              make_float2(fmaxf(u.x + m, 0.f), fmaxf(u.y + m, 0.f));
        }
      }
    }
    __syncthreads();

    // ---- acc2 += t @ W2 ----
    stream_tiles<HID / KT, NSTG>(W2, wbuf, tid, [&](const float* wb, int k0) {
      mma_tile<NPG, KSTR_F>(wb, hT + (size_t)k0 * KSTR_F + rg * GSTR_F, c0, acc2);
    });

    // ---- LayerNorm stats ----
    u64 s2[NPG], q2[NPG];
    #pragma unroll
    for (int p = 0; p < NPG; p++) {
      u64 s = acc2[0][p];
      u64 q = fmul2(acc2[0][p], acc2[0][p]);
      #pragma unroll
      for (int c = 1; c < 8; c++) {
        s = fadd2(s, acc2[c][p]);
        q = ffma2(acc2[c][p], acc2[c][p], q);
      }
      s2[p] = s; q2[p] = q;
    }
    #pragma unroll
    for (int off = 4; off <= 16; off <<= 1) {
      #pragma unroll
      for (int p = 0; p < NPG; p++) {
        s2[p] = fadd2(s2[p], __shfl_xor_sync(FULL_MASK, s2[p], off));
        q2[p] = fadd2(q2[p], __shfl_xor_sync(FULL_MASK, q2[p], off));
      }
    }
    if ((lane >> 2) == 0) {
      #pragma unroll
      for (int p = 0; p < NPG; p++) {
        red[((0 * 4 + warp) * 4 + rg) * NPG + p] = s2[p];
        red[((1 * 4 + warp) * 4 + rg) * NPG + p] = q2[p];
      }
    }
    __syncthreads();

    float2 mean2[NPG], rstd2[NPG];
    #pragma unroll
    for (int p = 0; p < NPG; p++) {
      u64 S = red[((0 * 4 + 0) * 4 + rg) * NPG + p];
      u64 Q = red[((1 * 4 + 0) * 4 + rg) * NPG + p];
      #pragma unroll
      for (int w = 1; w < 4; w++) {
        S = fadd2(S, red[((0 * 4 + w) * 4 + rg) * NPG + p]);
        Q = fadd2(Q, red[((1 * 4 + w) * 4 + rg) * NPG + p]);
      }
      float2 su = unpack2(S), qu = unpack2(Q);
      const float mx = su.x * (1.0f / HID), my = su.y * (1.0f / HID);
      mean2[p] = make_float2(mx, my);
      rstd2[p] = make_float2(rsqrtf(qu.x * (1.0f / HID) - mx * mx + 1e-5f),
                             rsqrtf(qu.y * (1.0f / HID) - my * my + 1e-5f));
    }

    // ---- normalize, mask, write back, new msg ----
    const float4 lga4 = *reinterpret_cast<const float4*>(lg + c0);
    const float4 lgc4 = *reinterpret_cast<const float4*>(lg + c0 + 4);
    const float4 lba4 = *reinterpret_cast<const float4*>(lb + c0);
    const float4 lbc4 = *reinterpret_cast<const float4*>(lb + c0 + 4);
    const float lgv[8] = {lga4.x, lga4.y, lga4.z, lga4.w, lgc4.x, lgc4.y, lgc4.z, lgc4.w};
    const float lbv[8] = {lba4.x, lba4.y, lba4.z, lba4.w, lbc4.x, lbc4.y, lbc4.z, lbc4.w};
    float msum[SPG][8];
    #pragma unroll
    for (int sp = 0; sp < SPG; sp++)
      #pragma unroll
      for (int c = 0; c < 8; c++) msum[sp][c] = 0.f;
    #pragma unroll
    for (int c = 0; c < 8; c++) {
      float* hcol = hT + (size_t)(c0 + c) * KSTR_F + rg * GSTR_F;
      #pragma unroll
      for (int p = 0; p < NPG; p++) {
        const int sp = (SPG == 2 && p >= NPG / 2) ? 1 : 0;
        const int nv = sp ? ncvB : ncvA;
        const int r0i = (SPG == 2) ? (2 * p) % NR : rbase + 2 * p;
        float2 u = unpack2(acc2[c][p]);
        float v0 = 0.f, v1 = 0.f;
        if (r0i     < nv) v0 = (u.x - mean2[p].x) * rstd2[p].x * lgv[c] + lbv[c];
        if (r0i + 1 < nv) v1 = (u.y - mean2[p].y) * rstd2[p].y * lgv[c] + lbv[c];
        *reinterpret_cast<float2*>(hcol + 2 * p) = make_float2(v0, v1);
        msum[sp][c] += v0 + v1;
      }
    }
    if constexpr (GPS == 2) {
      #pragma unroll
      for (int c = 0; c < 8; c++)
        msum[0][c] += __shfl_xor_sync(FULL_MASK, msum[0][c], 1);
      if ((rg & 1) == 0) {
        *reinterpret_cast<float4*>(msgs + g * HID + c0) =
            make_float4(msum[0][0] * invdA, msum[0][1] * invdA,
                        msum[0][2] * invdA, msum[0][3] * invdA);
        *reinterpret_cast<float4*>(msgs + g * HID + c0 + 4) =
            make_float4(msum[0][4] * invdA, msum[0][5] * invdA,
                        msum[0][6] * invdA, msum[0][7] * invdA);
      }
    } else {
      *reinterpret_cast<float4*>(msgs + g * HID + c0) =
          make_float4(msum[0][0] * invdA, msum[0][1] * invdA,
                      msum[0][2] * invdA, msum[0][3] * invdA);
      *reinterpret_cast<float4*>(msgs + g * HID + c0 + 4) =
          make_float4(msum[0][4] * invdA, msum[0][5] * invdA,
                      msum[0][6] * invdA, msum[0][7] * invdA);
      if constexpr (SPG == 2) {
        *reinterpret_cast<float4*>(msgs + (g + 1) * HID + c0) =
            make_float4(msum[1][0] * invdB, msum[1][1] * invdB,
                        msum[1][2] * invdB, msum[1][3] * invdB);
        *reinterpret_cast<float4*>(msgs + (g + 1) * HID + c0 + 4) =
            make_float4(msum[1][4] * invdB, msum[1][5] * invdB,
                        msum[1][6] * invdB, msum[1][7] * invdB);
      }
    }
    __syncthreads();
  }
  // msgs == per-sample g vector, hT == final h

  // ---------- dsm[s] = g·v2 + c ----------
  if (tid < GG) {
    const float* mg = msgs + tid * HID;
    float a0 = 0.f, a1 = 0.f, a2 = 0.f, a3 = 0.f;
    #pragma unroll 2
    for (int a = 0; a < HID; a += 4) {
      a0 = fmaf(mg[a + 0], d_v2[a + 0], a0);
      a1 = fmaf(mg[a + 1], d_v2[a + 1], a1);
      a2 = fmaf(mg[a + 2], d_v2[a + 2], a2);
      a3 = fmaf(mg[a + 3], d_v2[a + 3], a3);
    }
    dsm[tid] = d_c + (a0 + a1) + (a2 + a3);
  }

  // ---------- w[sp] = g_sp @ M + v1 via direct LDG ----------
  float wv[SPG][8];
  {
    const float4 va = *reinterpret_cast<const float4*>(d_v1 + c0);
    const float4 vc = *reinterpret_cast<const float4*>(d_v1 + c0 + 4);
    #pragma unroll
    for (int sp = 0; sp < SPG; sp++) {
      wv[sp][0] = va.x; wv[sp][1] = va.y; wv[sp][2] = va.z; wv[sp][3] = va.w;
      wv[sp][4] = vc.x; wv[sp][5] = vc.y; wv[sp][6] = vc.z; wv[sp][7] = vc.w;
    }
  }
  gemv_ldg<SPG>(d_M + c0, msgs + g * HID, wv);

  // ---------- pl partials ----------
  {
    u64 part[NPG];
    #pragma unroll
    for (int p = 0; p < NPG; p++) part[p] = 0ull;
    #pragma unroll
    for (int c = 0; c < 8; c++) {
      u64 h[NPG];
      ld_grp<NPG>(h, hT + (size_t)(c0 + c) * KSTR_F + rg * GSTR_F);
      #pragma unroll
      for (int p = 0; p < NPG; p++) {
        const int sp = (SPG == 2 && p >= NPG / 2) ? 1 : 0;
        part[p] = ffma2(h[p], bcast2(wv[sp][c]), part[p]);
      }
    }
    #pragma unroll
    for (int off = 4; off <= 16; off <<= 1)
      #pragma unroll
      for (int p = 0; p < NPG; p++)
        part[p] = fadd2(part[p], __shfl_xor_sync(FULL_MASK, part[p], off));
    if ((lane >> 2) == 0) {
      #pragma unroll
      for (int p = 0; p < NPG; p++)
        red[((0 * 4 + warp) * 4 + rg) * NPG + p] = part[p];
    }
  }
  __syncthreads();

  // ---------- pl output (all 20 slots; masked -> -1e9) ----------
  for (int idx = tid; idx < GG * NOBJ; idx += NT) {
    const int s = idx / NOBJ, i = idx % NOBJ;
    if (wok[s]) {
      float v = -1e9f;
      if (i < ncv[s]) {
        const int vr = s * NR + i;
        const int grp = vr / ROWSG, slot = vr % ROWSG;
        const int p = slot >> 1, hh = slot & 1;
        u64 S = red[((0 * 4 + 0) * 4 + grp) * NPG + p];
        #pragma unroll
        for (int w = 1; w < 4; w++)
          S = fadd2(S, red[((0 * 4 + w) * 4 + grp) * NPG + p]);
        float2 u = unpack2(S);
        v = (hh ? u.y : u.x) + dsm[s];
      }
      P.out[(size_t)P.B * 28 + (size_t)sid[s] * NOBJ + i] = v;
    }
  }

  // ---------- small heads from g-vector ----------
  for (int idx = tid; idx < GG * 28; idx += NT) {
    const int s = idx / 28;
    int cc = idx % 28;
    if (wok[s]) {
      const float* W; float bb; float* o; int no;
      if (cc < 8)       { W = P.ohW;  bb = P.ohb[cc];      no = 8;
                          o = P.out + (size_t)sid[s] * 8 + cc; }
      else if (cc < 18) { cc -= 8;  W = P.c1W; bb = P.c1b[cc]; no = 10;
                          o = P.out + (size_t)P.B * 8 + (size_t)sid[s] * 10 + cc; }
      else              { cc -= 18; W = P.c2W; bb = P.c2b[cc]; no = 10;
                          o = P.out + (size_t)P.B * 18 + (size_t)sid[s] * 10 + cc; }
      float a0 = bb, a1 = 0.f, a2 = 0.f, a3 = 0.f;
      const float* mg = msgs + s * HID;
      #pragma unroll 2
      for (int k = 0; k < HID; k += 4) {
        a0 = fmaf(mg[k + 0], W[(k + 0) * no + cc], a0);
        a1 = fmaf(mg[k + 1], W[(k + 1) * no + cc], a1);
        a2 = fmaf(mg[k + 2], W[(k + 2) * no + cc], a2);
        a3 = fmaf(mg[k + 3], W[(k + 3) * no + cc], a3);
      }
      *o = (a0 + a1) + (a2 + a3);
    }
  }
}

// ---------------- prep kernels ----------------
__global__ void tr_kernel(const float* __restrict__ pkW) {
  const int t = blockIdx.x, b = threadIdx.x;
  d_pkWT[t * HID + b] = pkW[b * HID + t];
}

__global__ void m_kernel(const float* __restrict__ pqW) {
  __shared__ float spq[HID];
  const int a = blockIdx.x, b = threadIdx.x;
  spq[b] = pqW[a * HID + b];
  __syncthreads();
  float s0 = 0.f, s1 = 0.f, s2 = 0.f, s3 = 0.f;
  #pragma unroll 4
  for (int t = 0; t < HID; t += 4) {
    s0 = fmaf(spq[t + 0], d_pkWT[(t + 0) * HID + b], s0);
    s1 = fmaf(spq[t + 1], d_pkWT[(t + 1) * HID + b], s1);
    s2 = fmaf(spq[t + 2], d_pkWT[(t + 2) * HID + b], s2);
    s3 = fmaf(spq[t + 3], d_pkWT[(t + 3) * HID + b], s3);
  }
  d_M[a * HID + b] = (s0 + s1) + (s2 + s3);
}

__global__ void vec_kernel(const float* __restrict__ pqW,
                           const float* __restrict__ pqb,
                           const float* __restrict__ pkb) {
  const int tid = threadIdx.x;
  if (tid < HID) {
    float a = 0.f;
    for (int t = 0; t < HID; t++)
      a = fmaf(pqb[t], d_pkWT[t * HID + tid], a);
    d_v1[tid] = a;
    if (tid == 0) {
      float cc = 0.f;
      for (int t = 0; t < HID; t++) cc = fmaf(pqb[t], pkb[t], cc);
      d_c = cc;
    }
  } else {
    const int a = tid - HID;
    float s = 0.f;
    for (int t = 0; t < HID; t++)
      s = fmaf(pqW[a * HID + t], pkb[t], s);
    d_v2[a] = s;
  }
}

__global__ void __launch_bounds__(1024, 1) pack_kernel(const int* __restrict__ nn_c, int B) {
  __shared__ int cnt[NBUCK], base[NBUCK];
  const int tid = threadIdx.x;
  if (tid < NBUCK) cnt[tid] = 0;
  __syncthreads();
  for (int i = tid; i < B; i += 1024) {
    int nc = min(max(nn_c[i], 0), NOBJ);
    atomicAdd(&cnt[bucket_of(nc)], 1);
  }
  __syncthreads();
  if (tid == 0) {
    int s = 0;
    for (int b = 0; b < NBUCK; b++) { base[b] = s; s += cnt[b]; }
    int cb = 0, sb = 0;
    for (int b = 0; b < NBUCK; b++) {
      d_cta_base[b] = cb;
      d_slot_base[b] = sb;
      const int gg = gg_of(b);
      cb += (cnt[b] + gg - 1) / gg;
      sb += cnt[b];
    }
    d_cta_base[NBUCK] = cb;
    d_slot_base[NBUCK] = sb;
  }
  __syncthreads();
  if (tid < NBUCK) cnt[tid] = 0;
  __syncthreads();
  for (int i = tid; i < B; i += 1024) {
    int nc = min(max(nn_c[i], 0), NOBJ);
    const int b = bucket_of(nc);
    int slot = base[b] + atomicAdd(&cnt[b], 1);
    d_perm[slot] = i;
  }
}

__global__ void __launch_bounds__(NT, 3) gnn_kernel(Params P) {
  extern __shared__ __align__(16) float sm[];
  const int c = blockIdx.x;
  if (c >= d_cta_base[NBUCK]) return;
  int b = 0;
  #pragma unroll
  for (int i = 1; i < NBUCK; i++)
    if (c >= d_cta_base[i]) b = i;
  const int gg = gg_of(b);
  const int sbase = d_slot_base[b] + (c - d_cta_base[b]) * gg;
  const int send = d_slot_base[b + 1];
  const int tid = threadIdx.x;
  switch (b) {
    case 0:  run<8, 4, 3>(P, sm, sbase, send, tid);  break;
    case 1:  run<4, 8, 3>(P, sm, sbase, send, tid);  break;
    case 2:  run<4, 10, 2>(P, sm, sbase, send, tid); break;
    case 3:  run<2, 12, 3>(P, sm, sbase, send, tid); break;
    case 4:  run<2, 16, 3>(P, sm, sbase, send, tid); break;
    default: run<2, 20, 3>(P, sm, sbase, send, tid); break;
  }
}

// smem = max over variants: HID*KSTR_F + NSTG*TILE_F + GG*HID + GG(dsm)
//   GG2,NR20,3st: 256*48 + 3*2048 + 512 + 16 = 18960 floats (75,840 B) <- max
constexpr int SMEM_BYTES = 18960 * 4;  // 3 CTAs/SM

}  // namespace

extern "C" void kernel_launch(void* const* d_in, const int* in_sizes, int n_in,
                              void* d_out, int out_size) {
  Params P;
  P.nf   = (const float*)d_in[0];
  P.nn_c = (const int*)d_in[1];
  P.neW  = (const float*)d_in[2];  P.neb  = (const float*)d_in[3];
  P.g1W1 = (const float*)d_in[4];  P.g1b1 = (const float*)d_in[5];
  P.g1W2 = (const float*)d_in[6];  P.g1b2 = (const float*)d_in[7];
  P.g2W1 = (const float*)d_in[8];  P.g2b1 = (const float*)d_in[9];
  P.g2W2 = (const float*)d_in[10]; P.g2b2 = (const float*)d_in[11];
  P.n1g  = (const float*)d_in[12]; P.n1b  = (const float*)d_in[13];
  P.n2g  = (const float*)d_in[14]; P.n2b  = (const float*)d_in[15];
  P.ohW  = (const float*)d_in[16]; P.ohb  = (const float*)d_in[17];
  P.c1W  = (const float*)d_in[18]; P.c1b  = (const float*)d_in[19];
  P.c2W  = (const float*)d_in[20]; P.c2b  = (const float*)d_in[21];
  P.pqW  = (const float*)d_in[22]; P.pqb  = (const float*)d_in[23];
  P.pkW  = (const float*)d_in[24]; P.pkb  = (const float*)d_in[25];
  P.out  = (float*)d_out;
  P.B    = in_sizes[1];

  cudaFuncSetAttribute(gnn_kernel, cudaFuncAttributeMaxDynamicSharedMemorySize,
                       SMEM_BYTES);

  tr_kernel<<<HID, HID>>>(P.pkW);
  m_kernel<<<HID, HID>>>(P.pqW);
  vec_kernel<<<1, 512>>>(P.pqW, P.pqb, P.pkb);
  pack_kernel<<<1, 1024>>>(P.nn_c, P.B);
  const int nblocks = (P.B + 1) / 2;
  gnn_kernel<<<nblocks, NT, SMEM_BYTES>>>(P);
}

// round 16
// speedup vs baseline: 1.0206x; 1.0206x over previous
#include <cuda_runtime.h>

namespace {

constexpr int HID  = 256;
constexpr int NOBJ = 20;
constexpr int NFD  = 16;
constexpr int NT   = 128;        // threads per block (fat threads: 8 cols each)
constexpr int KT   = 8;          // weight k-tile rows
constexpr int TILE_F = KT * HID; // floats per weight tile (2048)
constexpr int MAXB = 16384;
constexpr int NBUCK = 6;
constexpr unsigned FULL_MASK = 0xFFFFFFFFu;

using u64 = unsigned long long;

__device__ int d_perm[MAXB];
__device__ int d_cta_base[NBUCK + 1];
__device__ int d_slot_base[NBUCK + 1];

// Precomputed pointer-logit fusion: pl_i = h_i·(g@M + v1) + g·v2 + c
__device__ float d_M[HID * HID];
__device__ float d_pkWT[HID * HID];
__device__ float d_v1[HID];
__device__ float d_v2[HID];
__device__ float d_c;

struct Params {
  const float* __restrict__ nf;   const int* __restrict__ nn_c;
  const float* __restrict__ neW;  const float* __restrict__ neb;
  const float* __restrict__ g1W1; const float* __restrict__ g1b1;
  const float* __restrict__ g1W2; const float* __restrict__ g1b2;
  const float* __restrict__ g2W1; const float* __restrict__ g2b1;
  const float* __restrict__ g2W2; const float* __restrict__ g2b2;
  const float* __restrict__ n1g;  const float* __restrict__ n1b;
  const float* __restrict__ n2g;  const float* __restrict__ n2b;
  const float* __restrict__ ohW;  const float* __restrict__ ohb;
  const float* __restrict__ c1W;  const float* __restrict__ c1b;
  const float* __restrict__ c2W;  const float* __restrict__ c2b;
  const float* __restrict__ pqW;  const float* __restrict__ pqb;
  const float* __restrict__ pkW;  const float* __restrict__ pkb;
  float* __restrict__ out;
  int B;
};

__device__ __forceinline__ int bucket_of(int nc) {
  nc = nc > 0 ? nc : 1;
  if (nc <= 4)  return 0;
  if (nc <= 8)  return 1;
  if (nc <= 10) return 2;
  if (nc <= 12) return 3;
  if (nc <= 16) return 4;
  return 5;
}
__device__ __forceinline__ int gg_of(int b) {
  return (b == 0) ? 8 : ((b < 3) ? 4 : 2);
}

// ---------------- f32x2 packed helpers (carrier: u64, register-only) --------
__device__ __forceinline__ u64 ffma2(u64 a, u64 b, u64 c) {
  u64 r;
  asm("fma.rn.f32x2 %0, %1, %2, %3;" : "=l"(r) : "l"(a), "l"(b), "l"(c));
  return r;
}
__device__ __forceinline__ u64 bcast2(float w) {
  u64 r;
  asm("mov.b64 %0, {%1, %1};" : "=l"(r) : "f"(w));
  return r;
}
__device__ __forceinline__ u64 fadd2(u64 a, u64 b) { return ffma2(a, bcast2(1.0f), b); }
__device__ __forceinline__ u64 fmul2(u64 a, u64 b) { return ffma2(a, b, bcast2(0.0f)); }
__device__ __forceinline__ float2 unpack2(u64 v) {
  float2 f;
  asm("mov.b64 {%0, %1}, %2;" : "=f"(f.x), "=f"(f.y) : "l"(v));
  return f;
}

__device__ __forceinline__ void cp_async16(void* smem, const void* gmem) {
  unsigned s = (unsigned)__cvta_generic_to_shared(smem);
  asm volatile("cp.async.cg.shared.global [%0], [%1], 16;\n" ::"r"(s), "l"(gmem));
}
__device__ __forceinline__ void cp_commit() { asm volatile("cp.async.commit_group;\n"); }
__device__ __forceinline__ void cp_wait1()  { asm volatile("cp.async.wait_group 1;\n"); }
__device__ __forceinline__ void cp_wait0()  { asm volatile("cp.async.wait_group 0;\n"); }

__device__ __forceinline__ void load_tile(float* dst, const float* W, int k0, int tid) {
  const float4* src = reinterpret_cast<const float4*>(W + (size_t)k0 * HID);
  float4* d = reinterpret_cast<float4*>(dst);
  #pragma unroll
  for (int r = 0; r < TILE_F / 4 / NT; r++)
    cp_async16(&d[tid + r * NT], &src[tid + r * NT]);
}

// Stream NTILES weight tiles through an NSTAGES-buffer ring; 1 barrier/tile.
template <int NTILES, int NSTAGES, typename F>
__device__ __forceinline__ void stream_tiles(const float* __restrict__ W,
                                             float* wbuf, int tid, F&& consume) {
  if constexpr (NSTAGES == 3) {
    load_tile(wbuf + 0 * TILE_F, W, 0 * KT, tid);
    cp_commit();
    load_tile(wbuf + 1 * TILE_F, W, 1 * KT, tid);
    cp_commit();
    #pragma unroll 1
    for (int tt = 0; tt < NTILES; tt++) {
      cp_wait1();
      __syncthreads();
      if (tt + 2 < NTILES)
        load_tile(wbuf + ((tt + 2) % 3) * TILE_F, W, (tt + 2) * KT, tid);
      cp_commit();
      consume(wbuf + (tt % 3) * TILE_F, tt * KT);
    }
    __syncthreads();
  } else {
    load_tile(wbuf, W, 0, tid);
    cp_commit();
    #pragma unroll 1
    for (int tt = 0; tt < NTILES; tt++) {
      cp_wait0();
      __syncthreads();
      if (tt + 1 < NTILES) {
        load_tile(wbuf + ((tt + 1) & 1) * TILE_F, W, (tt + 1) * KT, tid);
        cp_commit();
      }
      consume(wbuf + (tt & 1) * TILE_F, tt * KT);
    }
    __syncthreads();
  }
}

template <int NPG>
__device__ __forceinline__ void ld_grp(u64* d, const float* p) {
  const u64* q = reinterpret_cast<const u64*>(p);
  #pragma unroll
  for (int i = 0; i + 2 <= NPG; i += 2) {
    ulonglong2 v = *reinterpret_cast<const ulonglong2*>(q + i);
    d[i] = v.x; d[i + 1] = v.y;
  }
  if constexpr (NPG & 1) d[NPG - 1] = q[NPG - 1];
}

template <int NPG, int KSTR_F>
__device__ __forceinline__ void mma_tile(const float* __restrict__ wb,
                                         const float* __restrict__ hsrc,
                                         int c0, u64 (&acc)[8][NPG]) {
  #pragma unroll 4
  for (int kk = 0; kk < KT; kk++) {
    const float4 wa = *reinterpret_cast<const float4*>(wb + kk * HID + c0);
    const float4 wc = *reinterpret_cast<const float4*>(wb + kk * HID + c0 + 4);
    u64 h[NPG];
    ld_grp<NPG>(h, hsrc + kk * KSTR_F);
    u64 w[8];
    w[0] = bcast2(wa.x); w[1] = bcast2(wa.y); w[2] = bcast2(wa.z); w[3] = bcast2(wa.w);
    w[4] = bcast2(wc.x); w[5] = bcast2(wc.y); w[6] = bcast2(wc.z); w[7] = bcast2(wc.w);
    #pragma unroll
    for (int p = 0; p < NPG; p++) {
      #pragma unroll
      for (int c = 0; c < 8; c++)
        acc[c][p] = ffma2(h[p], w[c], acc[c][p]);
    }
  }
}

// ------------------------------------------------------------------
// GG samples per CTA (GG in {2,4,8}); 4 row-groups always.
// ROWSG = GG*NR/4 rows per group; SPG = samples per group (GG8 -> 2).
// Virtual row vr = s*NR + i  ->  grp = vr/ROWSG, slot = vr%ROWSG.
// ------------------------------------------------------------------
template <int GG, int NR, int NSTG>
__device__ __forceinline__ void run(const Params& P, float* sm, int sbase,
                                    int send, int tid) {
  constexpr int ROWSG = GG * NR / 4;
  constexpr int SPG = (GG >= 8) ? 2 : 1;
  constexpr int GPS = (GG >= 4) ? 1 : 4 / GG;
  constexpr int NPG = ROWSG / 2;
  constexpr int GSTR_F = (((NPG * 8) + 15) & ~15) / 4;
  constexpr int KSTR_F = 4 * GSTR_F;

  float* hT   = sm;                       // HID * KSTR_F
  float* wbuf = hT + HID * KSTR_F;        // NSTG * TILE_F
  float* msgs = wbuf + NSTG * TILE_F;     // GG * HID
  float* dsm  = msgs + GG * HID;          // GG
  float* nfs  = wbuf;                     // overlay (embed phase only)
  u64*  red   = reinterpret_cast<u64*>(wbuf);  // overlay (between streams)

  const int lane = tid & 31, warp = tid >> 5;
  const int cg = tid >> 2, rg = tid & 3, c0 = cg * 8;
  const int g = (SPG == 2) ? rg * 2 : rg / GPS;
  const int rbase = (SPG == 2) ? 0 : (rg % GPS) * ROWSG;

  int sid[GG]; int ncv[GG]; float invd[GG]; bool wok[GG];
  #pragma unroll
  for (int s = 0; s < GG; s++) {
    const int ss = sbase + s;
    wok[s] = (ss < send);
    sid[s] = wok[s] ? d_perm[ss] : 0;
    int nc = wok[s] ? P.nn_c[sid[s]] : 0;
    ncv[s] = min(max(nc, 0), NOBJ);
    invd[s] = 1.0f / (float)(ncv[s] > 0 ? ncv[s] : 1);
  }
  int ncvA = 0, ncvB = 0; float invdA = 1.f, invdB = 1.f;
  #pragma unroll
  for (int s = 0; s < GG; s++) {
    if (s == g) { ncvA = ncv[s]; invdA = invd[s]; }
    if (SPG == 2 && s == g + 1) { ncvB = ncv[s]; invdB = invd[s]; }
  }

  // node features
  for (int idx = tid; idx < GG * 80; idx += NT) {
    const int s = idx / 80, o = idx % 80;
    reinterpret_cast<float4*>(nfs)[idx] =
        reinterpret_cast<const float4*>(P.nf + (size_t)sid[s] * (NOBJ * NFD))[o];
  }
  __syncthreads();

  // ---------- node embed ----------
  #pragma unroll
  for (int half = 0; half < 2; half++) {
    const int j = tid + half * NT;
    float wv[NFD];
    #pragma unroll
    for (int k = 0; k < NFD; k++) wv[k] = P.neW[k * HID + j];
    const float bias = P.neb[j];
    #pragma unroll
    for (int s = 0; s < GG; s++) {
      float ms = 0.f;
      #pragma unroll
      for (int i = 0; i < NR; i += 2) {
        float a2[2];
        #pragma unroll
        for (int t = 0; t < 2; t++) {
          const float4* rp = reinterpret_cast<const float4*>(nfs + s * 320 + (i + t) * NFD);
          float4 r0 = rp[0], r1 = rp[1], r2 = rp[2], r3 = rp[3];
          float a = bias;
          a = fmaf(r0.x, wv[0], a);  a = fmaf(r0.y, wv[1], a);
          a = fmaf(r0.z, wv[2], a);  a = fmaf(r0.w, wv[3], a);
          a = fmaf(r1.x, wv[4], a);  a = fmaf(r1.y, wv[5], a);
          a = fmaf(r1.z, wv[6], a);  a = fmaf(r1.w, wv[7], a);
          a = fmaf(r2.x, wv[8], a);  a = fmaf(r2.y, wv[9], a);
          a = fmaf(r2.z, wv[10], a); a = fmaf(r2.w, wv[11], a);
          a = fmaf(r3.x, wv[12], a); a = fmaf(r3.y, wv[13], a);
          a = fmaf(r3.z, wv[14], a); a = fmaf(r3.w, wv[15], a);
          a2[t] = a;
          if (i + t < ncv[s]) ms += a;
        }
        const int vr = s * NR + i;
        const int grp = vr / ROWSG, slot = vr % ROWSG;
        *reinterpret_cast<float2*>(hT + (size_t)j * KSTR_F + grp * GSTR_F + slot) =
            make_float2(a2[0], a2[1]);
      }
      msgs[s * HID + j] = ms * invd[s];
    }
  }
  __syncthreads();

  // ---------- two message-passing layers ----------
  #pragma unroll 1
  for (int L = 0; L < 2; L++) {
    const float* W1 = L ? P.g2W1 : P.g1W1;  const float* b1 = L ? P.g2b1 : P.g1b1;
    const float* W2 = L ? P.g2W2 : P.g1W2;  const float* b2 = L ? P.g2b2 : P.g1b2;
    const float* lg = L ? P.n2g  : P.n1g;   const float* lb = L ? P.n2b  : P.n1b;

    // ---- t = relu([h | msg] @ W1 + b1): one 64-tile stream ----
    u64 t2[8][NPG];
    float mac[SPG][8];
    #pragma unroll
    for (int sp = 0; sp < SPG; sp++)
      #pragma unroll
      for (int c = 0; c < 8; c++) mac[sp][c] = 0.f;
    #pragma unroll
    for (int c = 0; c < 8; c++)
      #pragma unroll
      for (int p = 0; p < NPG; p++) t2[c][p] = 0ull;
    stream_tiles<512 / KT, NSTG>(W1, wbuf, tid, [&](const float* wb, int k0) {
      if (k0 < HID) {
        mma_tile<NPG, KSTR_F>(wb, hT + (size_t)k0 * KSTR_F + rg * GSTR_F, c0, t2);
      } else {
        #pragma unroll 4
        for (int kk = 0; kk < KT; kk++) {
          const float4 wa = *reinterpret_cast<const float4*>(wb + kk * HID + c0);
          const float4 wc = *reinterpret_cast<const float4*>(wb + kk * HID + c0 + 4);
          const int km = k0 + kk - HID;
          #pragma unroll
          for (int sp = 0; sp < SPG; sp++) {
            const float m = msgs[(g + sp) * HID + km];
            mac[sp][0] = fmaf(m, wa.x, mac[sp][0]); mac[sp][1] = fmaf(m, wa.y, mac[sp][1]);
            mac[sp][2] = fmaf(m, wa.z, mac[sp][2]); mac[sp][3] = fmaf(m, wa.w, mac[sp][3]);
            mac[sp][4] = fmaf(m, wc.x, mac[sp][4]); mac[sp][5] = fmaf(m, wc.y, mac[sp][5]);
            mac[sp][6] = fmaf(m, wc.z, mac[sp][6]); mac[sp][7] = fmaf(m, wc.w, mac[sp][7]);
          }
        }
      }
    });

    // ---- epilogue 1: acc2 = h_old + b2 (residual pre-add); hT <- relu(t) ----
    u64 acc2[8][NPG];
    {
      const float4 b1a = *reinterpret_cast<const float4*>(b1 + c0);
      const float4 b1c = *reinterpret_cast<const float4*>(b1 + c0 + 4);
      const float4 b2a = *reinterpret_cast<const float4*>(b2 + c0);
      const float4 b2c = *reinterpret_cast<const float4*>(b2 + c0 + 4);
      const float b1v[8] = {b1a.x, b1a.y, b1a.z, b1a.w, b1c.x, b1c.y, b1c.z, b1c.w};
      const float b2v[8] = {b2a.x, b2a.y, b2a.z, b2a.w, b2c.x, b2c.y, b2c.z, b2c.w};
      #pragma unroll
      for (int c = 0; c < 8; c++) {
        float* hcol = hT + (size_t)(c0 + c) * KSTR_F + rg * GSTR_F;
        u64 hold[NPG];
        ld_grp<NPG>(hold, hcol);
        const u64 b2d = bcast2(b2v[c]);
        #pragma unroll
        for (int p = 0; p < NPG; p++) acc2[c][p] = fadd2(hold[p], b2d);
        #pragma unroll
        for (int p = 0; p < NPG; p++) {
          const int sp = (SPG == 2 && p >= NPG / 2) ? 1 : 0;
          const float m = mac[sp][c] + b1v[c];
          float2 u = unpack2(t2[c][p]);
          *reinterpret_cast<float2*>(hcol + 2 * p) =
              make_float2(fmaxf(u.x + m, 0.f), fmaxf(u.y + m, 0.f));
        }
      }
    }
    __syncthreads();

    // ---- acc2 += t @ W2 ----
    stream_tiles<HID / KT, NSTG>(W2, wbuf, tid, [&](const float* wb, int k0) {
      mma_tile<NPG, KSTR_F>(wb, hT + (size_t)k0 * KSTR_F + rg * GSTR_F, c0, acc2);
    });

    // ---- LayerNorm stats ----
    u64 s2[NPG], q2[NPG];
    #pragma unroll
    for (int p = 0; p < NPG; p++) {
      u64 s = acc2[0][p];
      u64 q = fmul2(acc2[0][p], acc2[0][p]);
      #pragma unroll
      for (int c = 1; c < 8; c++) {
        s = fadd2(s, acc2[c][p]);
        q = ffma2(acc2[c][p], acc2[c][p], q);
      }
      s2[p] = s; q2[p] = q;
    }
    #pragma unroll
    for (int off = 4; off <= 16; off <<= 1) {
      #pragma unroll
      for (int p = 0; p < NPG; p++) {
        s2[p] = fadd2(s2[p], __shfl_xor_sync(FULL_MASK, s2[p], off));
        q2[p] = fadd2(q2[p], __shfl_xor_sync(FULL_MASK, q2[p], off));
      }
    }
    if ((lane >> 2) == 0) {
      #pragma unroll
      for (int p = 0; p < NPG; p++) {
        red[((0 * 4 + warp) * 4 + rg) * NPG + p] = s2[p];
        red[((1 * 4 + warp) * 4 + rg) * NPG + p] = q2[p];
      }
    }
    __syncthreads();

    float2 mean2[NPG], rstd2[NPG];
    #pragma unroll
    for (int p = 0; p < NPG; p++) {
      u64 S = red[((0 * 4 + 0) * 4 + rg) * NPG + p];
      u64 Q = red[((1 * 4 + 0) * 4 + rg) * NPG + p];
      #pragma unroll
      for (int w = 1; w < 4; w++) {
        S = fadd2(S, red[((0 * 4 + w) * 4 + rg) * NPG + p]);
        Q = fadd2(Q, red[((1 * 4 + w) * 4 + rg) * NPG + p]);
      }
      float2 su = unpack2(S), qu = unpack2(Q);
      const float mx = su.x * (1.0f / HID), my = su.y * (1.0f / HID);
      mean2[p] = make_float2(mx, my);
      rstd2[p] = make_float2(rsqrtf(qu.x * (1.0f / HID) - mx * mx + 1e-5f),
                             rsqrtf(qu.y * (1.0f / HID) - my * my + 1e-5f));
    }

    // ---- normalize, mask, write back, new msg ----
    const float4 lga4 = *reinterpret_cast<const float4*>(lg + c0);
    const float4 lgc4 = *reinterpret_cast<const float4*>(lg + c0 + 4);
    const float4 lba4 = *reinterpret_cast<const float4*>(lb + c0);
    const float4 lbc4 = *reinterpret_cast<const float4*>(lb + c0 + 4);
    const float lgv[8] = {lga4.x, lga4.y, lga4.z, lga4.w, lgc4.x, lgc4.y, lgc4.z, lgc4.w};
    const float lbv[8] = {lba4.x, lba4.y, lba4.z, lba4.w, lbc4.x, lbc4.y, lbc4.z, lbc4.w};
    float msum[SPG][8];
    #pragma unroll
    for (int sp = 0; sp < SPG; sp++)
      #pragma unroll
      for (int c = 0; c < 8; c++) msum[sp][c] = 0.f;
    #pragma unroll
    for (int c = 0; c < 8; c++) {
      float* hcol = hT + (size_t)(c0 + c) * KSTR_F + rg * GSTR_F;
      #pragma unroll
      for (int p = 0; p < NPG; p++) {
        const int sp = (SPG == 2 && p >= NPG / 2) ? 1 : 0;
        const int nv = sp ? ncvB : ncvA;
        const int r0i = (SPG == 2) ? (2 * p) % NR : rbase + 2 * p;
        float2 u = unpack2(acc2[c][p]);
        float v0 = 0.f, v1 = 0.f;
        if (r0i     < nv) v0 = (u.x - mean2[p].x) * rstd2[p].x * lgv[c] + lbv[c];
        if (r0i + 1 < nv) v1 = (u.y - mean2[p].y) * rstd2[p].y * lgv[c] + lbv[c];
        *reinterpret_cast<float2*>(hcol + 2 * p) = make_float2(v0, v1);
        msum[sp][c] += v0 + v1;
      }
    }
    if constexpr (GPS == 2) {
      #pragma unroll
      for (int c = 0; c < 8; c++)
        msum[0][c] += __shfl_xor_sync(FULL_MASK, msum[0][c], 1);
      if ((rg & 1) == 0) {
        *reinterpret_cast<float4*>(msgs + g * HID + c0) =
            make_float4(msum[0][0] * invdA, msum[0][1] * invdA,
                        msum[0][2] * invdA, msum[0][3] * invdA);
        *reinterpret_cast<float4*>(msgs + g * HID + c0 + 4) =
            make_float4(msum[0][4] * invdA, msum[0][5] * invdA,
                        msum[0][6] * invdA, msum[0][7] * invdA);
      }
    } else {
      *reinterpret_cast<float4*>(msgs + g * HID + c0) =
          make_float4(msum[0][0] * invdA, msum[0][1] * invdA,
                      msum[0][2] * invdA, msum[0][3] * invdA);
      *reinterpret_cast<float4*>(msgs + g * HID + c0 + 4) =
          make_float4(msum[0][4] * invdA, msum[0][5] * invdA,
                      msum[0][6] * invdA, msum[0][7] * invdA);
      if constexpr (SPG == 2) {
        *reinterpret_cast<float4*>(msgs + (g + 1) * HID + c0) =
            make_float4(msum[1][0] * invdB, msum[1][1] * invdB,
                        msum[1][2] * invdB, msum[1][3] * invdB);
        *reinterpret_cast<float4*>(msgs + (g + 1) * HID + c0 + 4) =
            make_float4(msum[1][4] * invdB, msum[1][5] * invdB,
                        msum[1][6] * invdB, msum[1][7] * invdB);
      }
    }
    __syncthreads();
  }
  // msgs == per-sample g vector, hT == final h

  // ---------- dsm[s] = g·v2 + c ----------
  if (tid < GG) {
    const float* mg = msgs + tid * HID;
    float a0 = 0.f, a1 = 0.f, a2 = 0.f, a3 = 0.f;
    #pragma unroll 2
    for (int a = 0; a < HID; a += 4) {
      a0 = fmaf(mg[a + 0], d_v2[a + 0], a0);
      a1 = fmaf(mg[a + 1], d_v2[a + 1], a1);
      a2 = fmaf(mg[a + 2], d_v2[a + 2], a2);
      a3 = fmaf(mg[a + 3], d_v2[a + 3], a3);
    }
    dsm[tid] = d_c + (a0 + a1) + (a2 + a3);
  }

  // ---------- w[sp] = g_sp @ M + v1 (streamed) ----------
  float wv[SPG][8];
  {
    const float4 va = *reinterpret_cast<const float4*>(d_v1 + c0);
    const float4 vc = *reinterpret_cast<const float4*>(d_v1 + c0 + 4);
    #pragma unroll
    for (int sp = 0; sp < SPG; sp++) {
      wv[sp][0] = va.x; wv[sp][1] = va.y; wv[sp][2] = va.z; wv[sp][3] = va.w;
      wv[sp][4] = vc.x; wv[sp][5] = vc.y; wv[sp][6] = vc.z; wv[sp][7] = vc.w;
    }
  }
  stream_tiles<HID / KT, NSTG>(d_M, wbuf, tid, [&](const float* wb, int k0) {
    #pragma unroll 4
    for (int kk = 0; kk < KT; kk++) {
      const float4 wa = *reinterpret_cast<const float4*>(wb + kk * HID + c0);
      const float4 wc = *reinterpret_cast<const float4*>(wb + kk * HID + c0 + 4);
      #pragma unroll
      for (int sp = 0; sp < SPG; sp++) {
        const float m = msgs[(g + sp) * HID + k0 + kk];
        wv[sp][0] = fmaf(m, wa.x, wv[sp][0]); wv[sp][1] = fmaf(m, wa.y, wv[sp][1]);
        wv[sp][2] = fmaf(m, wa.z, wv[sp][2]); wv[sp][3] = fmaf(m, wa.w, wv[sp][3]);
        wv[sp][4] = fmaf(m, wc.x, wv[sp][4]); wv[sp][5] = fmaf(m, wc.y, wv[sp][5]);
        wv[sp][6] = fmaf(m, wc.z, wv[sp][6]); wv[sp][7] = fmaf(m, wc.w, wv[sp][7]);
      }
    }
  });

  // ---------- pl partials ----------
  {
    u64 part[NPG];
    #pragma unroll
    for (int p = 0; p < NPG; p++) part[p] = 0ull;
    #pragma unroll
    for (int c = 0; c < 8; c++) {
      u64 h[NPG];
      ld_grp<NPG>(h, hT + (size_t)(c0 + c) * KSTR_F + rg * GSTR_F);
      #pragma unroll
      for (int p = 0; p < NPG; p++) {
        const int sp = (SPG == 2 && p >= NPG / 2) ? 1 : 0;
        part[p] = ffma2(h[p], bcast2(wv[sp][c]), part[p]);
      }
    }
    #pragma unroll
    for (int off = 4; off <= 16; off <<= 1)
      #pragma unroll
      for (int p = 0; p < NPG; p++)
        part[p] = fadd2(part[p], __shfl_xor_sync(FULL_MASK, part[p], off));
    if ((lane >> 2) == 0) {
      #pragma unroll
      for (int p = 0; p < NPG; p++)
        red[((0 * 4 + warp) * 4 + rg) * NPG + p] = part[p];
    }
  }
  __syncthreads();

  // ---------- pl output (all 20 slots; masked -> -1e9) ----------
  for (int idx = tid; idx < GG * NOBJ; idx += NT) {
    const int s = idx / NOBJ, i = idx % NOBJ;
    if (wok[s]) {
      float v = -1e9f;
      if (i < ncv[s]) {
        const int vr = s * NR + i;
        const int grp = vr / ROWSG, slot = vr % ROWSG;
        const int p = slot >> 1, hh = slot & 1;
        u64 S = red[((0 * 4 + 0) * 4 + grp) * NPG + p];
        #pragma unroll
        for (int w = 1; w < 4; w++)
          S = fadd2(S, red[((0 * 4 + w) * 4 + grp) * NPG + p]);
        float2 u = unpack2(S);
        v = (hh ? u.y : u.x) + dsm[s];
      }
      P.out[(size_t)P.B * 28 + (size_t)sid[s] * NOBJ + i] = v;
    }
  }

  // ---------- small heads from g-vector ----------
  for (int idx = tid; idx < GG * 28; idx += NT) {
    const int s = idx / 28;
    int cc = idx % 28;
    if (wok[s]) {
      const float* W; float bb; float* o; int no;
      if (cc < 8)       { W = P.ohW;  bb = P.ohb[cc];      no = 8;
                          o = P.out + (size_t)sid[s] * 8 + cc; }
      else if (cc < 18) { cc -= 8;  W = P.c1W; bb = P.c1b[cc]; no = 10;
                          o = P.out + (size_t)P.B * 8 + (size_t)sid[s] * 10 + cc; }
      else              { cc -= 18; W = P.c2W; bb = P.c2b[cc]; no = 10;
                          o = P.out + (size_t)P.B * 18 + (size_t)sid[s] * 10 + cc; }
      float a0 = bb, a1 = 0.f, a2 = 0.f, a3 = 0.f;
      const float* mg = msgs + s * HID;
      #pragma unroll 2
      for (int k = 0; k < HID; k += 4) {
        a0 = fmaf(mg[k + 0], W[(k + 0) * no + cc], a0);
        a1 = fmaf(mg[k + 1], W[(k + 1) * no + cc], a1);
        a2 = fmaf(mg[k + 2], W[(k + 2) * no + cc], a2);
        a3 = fmaf(mg[k + 3], W[(k + 3) * no + cc], a3);
      }
      *o = (a0 + a1) + (a2 + a3);
    }
  }
}

// ---------------- prep kernels ----------------
__global__ void tr_kernel(const float* __restrict__ pkW) {
  const int t = blockIdx.x, b = threadIdx.x;
  d_pkWT[t * HID + b] = pkW[b * HID + t];
}

__global__ void m_kernel(const float* __restrict__ pqW) {
  __shared__ float spq[HID];
  const int a = blockIdx.x, b = threadIdx.x;
  spq[b] = pqW[a * HID + b];
  __syncthreads();
  float s0 = 0.f, s1 = 0.f, s2 = 0.f, s3 = 0.f;
  #pragma unroll 4
  for (int t = 0; t < HID; t += 4) {
    s0 = fmaf(spq[t + 0], d_pkWT[(t + 0) * HID + b], s0);
    s1 = fmaf(spq[t + 1], d_pkWT[(t + 1) * HID + b], s1);
    s2 = fmaf(spq[t + 2], d_pkWT[(t + 2) * HID + b], s2);
    s3 = fmaf(spq[t + 3], d_pkWT[(t + 3) * HID + b], s3);
  }
  d_M[a * HID + b] = (s0 + s1) + (s2 + s3);
}

__global__ void vec_kernel(const float* __restrict__ pqW,
                           const float* __restrict__ pqb,
                           const float* __restrict__ pkb) {
  const int tid = threadIdx.x;
  if (tid < HID) {
    float a = 0.f;
    for (int t = 0; t < HID; t++)
      a = fmaf(pqb[t], d_pkWT[t * HID + tid], a);
    d_v1[tid] = a;
    if (tid == 0) {
      float cc = 0.f;
      for (int t = 0; t < HID; t++) cc = fmaf(pqb[t], pkb[t], cc);
      d_c = cc;
    }
  } else {
    const int a = tid - HID;
    float s = 0.f;
    for (int t = 0; t < HID; t++)
      s = fmaf(pqW[a * HID + t], pkb[t], s);
    d_v2[a] = s;
  }
}

// Warp-aggregated bucket counting: one atomic per warp per bucket.
// NOTE: shuffles use the ballot mask m (exact participant set), not FULL_MASK.
__global__ void __launch_bounds__(1024, 1) pack_kernel(const int* __restrict__ nn_c, int B) {
  __shared__ int cnt[NBUCK], base[NBUCK];
  const int tid = threadIdx.x;
  const int lane = tid & 31;
  const unsigned lt = (1u << lane) - 1u;
  if (tid < NBUCK) cnt[tid] = 0;
  __syncthreads();
  for (int i = tid; i < B; i += 1024) {
    const int b = bucket_of(min(max(nn_c[i], 0), NOBJ));
    #pragma unroll
    for (int bk = 0; bk < NBUCK; bk++) {
      const unsigned m = __ballot_sync(FULL_MASK, b == bk);
      if (b == bk && (m & lt) == 0) atomicAdd(&cnt[bk], __popc(m));
    }
  }
  __syncthreads();
  if (tid == 0) {
    int s = 0;
    for (int b = 0; b < NBUCK; b++) { base[b] = s; s += cnt[b]; }
    int cb = 0, sb = 0;
    for (int b = 0; b < NBUCK; b++) {
      d_cta_base[b] = cb;
      d_slot_base[b] = sb;
      const int gg = gg_of(b);
      cb += (cnt[b] + gg - 1) / gg;
      sb += cnt[b];
    }
    d_cta_base[NBUCK] = cb;
    d_slot_base[NBUCK] = sb;
  }
  __syncthreads();
  if (tid < NBUCK) cnt[tid] = 0;
  __syncthreads();
  for (int i = tid; i < B; i += 1024) {
    const int b = bucket_of(min(max(nn_c[i], 0), NOBJ));
    int slot = 0;
    #pragma unroll
    for (int bk = 0; bk < NBUCK; bk++) {
      const unsigned m = __ballot_sync(FULL_MASK, b == bk);
      if (b == bk) {
        int wb = 0;
        if ((m & lt) == 0) wb = atomicAdd(&cnt[bk], __popc(m));
        wb = __shfl_sync(m, wb, __ffs(m) - 1);   // mask = participants only
        slot = base[bk] + wb + __popc(m & lt);
      }
    }
    d_perm[slot] = i;
  }
}

__global__ void __launch_bounds__(NT, 3) gnn_kernel(Params P) {
  extern __shared__ __align__(16) float sm[];
  const int c = blockIdx.x;
  if (c >= d_cta_base[NBUCK]) return;
  int b = 0;
  #pragma unroll
  for (int i = 1; i < NBUCK; i++)
    if (c >= d_cta_base[i]) b = i;
  const int gg = gg_of(b);
  const int sbase = d_slot_base[b] + (c - d_cta_base[b]) * gg;
  const int send = d_slot_base[b + 1];
  const int tid = threadIdx.x;
  switch (b) {
    case 0:  run<8, 4, 3>(P, sm, sbase, send, tid);  break;
    case 1:  run<4, 8, 3>(P, sm, sbase, send, tid);  break;
    case 2:  run<4, 10, 2>(P, sm, sbase, send, tid); break;
    case 3:  run<2, 12, 3>(P, sm, sbase, send, tid); break;
    case 4:  run<2, 16, 3>(P, sm, sbase, send, tid); break;
    default: run<2, 20, 3>(P, sm, sbase, send, tid); break;
  }
}

// smem = max over variants: HID*KSTR_F + NSTG*TILE_F + GG*HID + GG(dsm)
//   GG2,NR20,3st: 256*48 + 3*2048 + 512 + 16 = 18960 floats (75,840 B) <- max
constexpr int SMEM_BYTES = 18960 * 4;  // 3 CTAs/SM

}  // namespace

extern "C" void kernel_launch(void* const* d_in, const int* in_sizes, int n_in,
                              void* d_out, int out_size) {
  Params P;
  P.nf   = (const float*)d_in[0];
  P.nn_c = (const int*)d_in[1];
  P.neW  = (const float*)d_in[2];  P.neb  = (const float*)d_in[3];
  P.g1W1 = (const float*)d_in[4];  P.g1b1 = (const float*)d_in[5];
  P.g1W2 = (const float*)d_in[6];  P.g1b2 = (const float*)d_in[7];
  P.g2W1 = (const float*)d_in[8];  P.g2b1 = (const float*)d_in[9];
  P.g2W2 = (const float*)d_in[10]; P.g2b2 = (const float*)d_in[11];
  P.n1g  = (const float*)d_in[12]; P.n1b  = (const float*)d_in[13];
  P.n2g  = (const float*)d_in[14]; P.n2b  = (const float*)d_in[15];
  P.ohW  = (const float*)d_in[16]; P.ohb  = (const float*)d_in[17];
  P.c1W  = (const float*)d_in[18]; P.c1b  = (const float*)d_in[19];
  P.c2W  = (const float*)d_in[20]; P.c2b  = (const float*)d_in[21];
  P.pqW  = (const float*)d_in[22]; P.pqb  = (const float*)d_in[23];
  P.pkW  = (const float*)d_in[24]; P.pkb  = (const float*)d_in[25];
  P.out  = (float*)d_out;
  P.B    = in_sizes[1];

  cudaFuncSetAttribute(gnn_kernel, cudaFuncAttributeMaxDynamicSharedMemorySize,
                       SMEM_BYTES);

  tr_kernel<<<HID, HID>>>(P.pkW);
  m_kernel<<<HID, HID>>>(P.pqW);
  vec_kernel<<<1, 512>>>(P.pqW, P.pqb, P.pkb);
  pack_kernel<<<1, 1024>>>(P.nn_c, P.B);
  const int nblocks = (P.B + 1) / 2;
  gnn_kernel<<<nblocks, NT, SMEM_BYTES>>>(P);
}

// round 17
// speedup vs baseline: 1.0343x; 1.0135x over previous
#include <cuda_runtime.h>

namespace {

constexpr int HID  = 256;
constexpr int NOBJ = 20;
constexpr int NFD  = 16;
constexpr int NT   = 128;        // threads per block (fat threads: 8 cols each)
constexpr int KT   = 8;          // weight k-tile rows
constexpr int TILE_F = KT * HID; // floats per weight tile (2048)
constexpr int MAXB = 16384;
constexpr int NBUCK = 6;
constexpr unsigned FULL_MASK = 0xFFFFFFFFu;

using u64 = unsigned long long;

__device__ int d_perm[MAXB];
__device__ int d_cta_base[NBUCK + 1];
__device__ int d_slot_base[NBUCK + 1];
__device__ int d_bcnt[NBUCK];    // histogram (count pass)
__device__ int d_ticket[NBUCK];  // scatter tickets

// Precomputed pointer-logit fusion: pl_i = h_i·(g@M + v1) + g·v2 + c
__device__ float d_M[HID * HID];
__device__ float d_pkWT[HID * HID];
__device__ float d_v1[HID];
__device__ float d_v2[HID];
__device__ float d_c;

struct Params {
  const float* __restrict__ nf;   const int* __restrict__ nn_c;
  const float* __restrict__ neW;  const float* __restrict__ neb;
  const float* __restrict__ g1W1; const float* __restrict__ g1b1;
  const float* __restrict__ g1W2; const float* __restrict__ g1b2;
  const float* __restrict__ g2W1; const float* __restrict__ g2b1;
  const float* __restrict__ g2W2; const float* __restrict__ g2b2;
  const float* __restrict__ n1g;  const float* __restrict__ n1b;
  const float* __restrict__ n2g;  const float* __restrict__ n2b;
  const float* __restrict__ ohW;  const float* __restrict__ ohb;
  const float* __restrict__ c1W;  const float* __restrict__ c1b;
  const float* __restrict__ c2W;  const float* __restrict__ c2b;
  const float* __restrict__ pqW;  const float* __restrict__ pqb;
  const float* __restrict__ pkW;  const float* __restrict__ pkb;
  float* __restrict__ out;
  int B;
};

__device__ __forceinline__ int bucket_of(int nc) {
  nc = nc > 0 ? nc : 1;
  if (nc <= 4)  return 0;
  if (nc <= 8)  return 1;
  if (nc <= 10) return 2;
  if (nc <= 12) return 3;
  if (nc <= 16) return 4;
  return 5;
}
__device__ __forceinline__ int gg_of(int b) {
  return (b == 0) ? 8 : ((b < 3) ? 4 : 2);
}

// ---------------- f32x2 packed helpers (carrier: u64, register-only) --------
__device__ __forceinline__ u64 ffma2(u64 a, u64 b, u64 c) {
  u64 r;
  asm("fma.rn.f32x2 %0, %1, %2, %3;" : "=l"(r) : "l"(a), "l"(b), "l"(c));
  return r;
}
__device__ __forceinline__ u64 bcast2(float w) {
  u64 r;
  asm("mov.b64 %0, {%1, %1};" : "=l"(r) : "f"(w));
  return r;
}
__device__ __forceinline__ u64 fadd2(u64 a, u64 b) { return ffma2(a, bcast2(1.0f), b); }
__device__ __forceinline__ u64 fmul2(u64 a, u64 b) { return ffma2(a, b, bcast2(0.0f)); }
__device__ __forceinline__ float2 unpack2(u64 v) {
  float2 f;
  asm("mov.b64 {%0, %1}, %2;" : "=f"(f.x), "=f"(f.y) : "l"(v));
  return f;
}

__device__ __forceinline__ void cp_async16(void* smem, const void* gmem) {
  unsigned s = (unsigned)__cvta_generic_to_shared(smem);
  asm volatile("cp.async.cg.shared.global [%0], [%1], 16;\n" ::"r"(s), "l"(gmem));
}
__device__ __forceinline__ void cp_commit() { asm volatile("cp.async.commit_group;\n"); }
__device__ __forceinline__ void cp_wait1()  { asm volatile("cp.async.wait_group 1;\n"); }
__device__ __forceinline__ void cp_wait0()  { asm volatile("cp.async.wait_group 0;\n"); }

__device__ __forceinline__ void load_tile(float* dst, const float* W, int k0, int tid) {
  const float4* src = reinterpret_cast<const float4*>(W + (size_t)k0 * HID);
  float4* d = reinterpret_cast<float4*>(dst);
  #pragma unroll
  for (int r = 0; r < TILE_F / 4 / NT; r++)
    cp_async16(&d[tid + r * NT], &src[tid + r * NT]);
}

// Stream NTILES weight tiles through an NSTAGES-buffer ring; 1 barrier/tile.
template <int NTILES, int NSTAGES, typename F>
__device__ __forceinline__ void stream_tiles(const float* __restrict__ W,
                                             float* wbuf, int tid, F&& consume) {
  if constexpr (NSTAGES == 3) {
    load_tile(wbuf + 0 * TILE_F, W, 0 * KT, tid);
    cp_commit();
    load_tile(wbuf + 1 * TILE_F, W, 1 * KT, tid);
    cp_commit();
    #pragma unroll 1
    for (int tt = 0; tt < NTILES; tt++) {
      cp_wait1();
      __syncthreads();
      if (tt + 2 < NTILES)
        load_tile(wbuf + ((tt + 2) % 3) * TILE_F, W, (tt + 2) * KT, tid);
      cp_commit();
      consume(wbuf + (tt % 3) * TILE_F, tt * KT);
    }
    __syncthreads();
  } else {
    load_tile(wbuf, W, 0, tid);
    cp_commit();
    #pragma unroll 1
    for (int tt = 0; tt < NTILES; tt++) {
      cp_wait0();
      __syncthreads();
      if (tt + 1 < NTILES) {
        load_tile(wbuf + ((tt + 1) & 1) * TILE_F, W, (tt + 1) * KT, tid);
        cp_commit();
      }
      consume(wbuf + (tt & 1) * TILE_F, tt * KT);
    }
    __syncthreads();
  }
}

template <int NPG>
__device__ __forceinline__ void ld_grp(u64* d, const float* p) {
  const u64* q = reinterpret_cast<const u64*>(p);
  #pragma unroll
  for (int i = 0; i + 2 <= NPG; i += 2) {
    ulonglong2 v = *reinterpret_cast<const ulonglong2*>(q + i);
    d[i] = v.x; d[i + 1] = v.y;
  }
  if constexpr (NPG & 1) d[NPG - 1] = q[NPG - 1];
}

template <int NPG, int KSTR_F>
__device__ __forceinline__ void mma_tile(const float* __restrict__ wb,
                                         const float* __restrict__ hsrc,
                                         int c0, u64 (&acc)[8][NPG]) {
  #pragma unroll 4
  for (int kk = 0; kk < KT; kk++) {
    const float4 wa = *reinterpret_cast<const float4*>(wb + kk * HID + c0);
    const float4 wc = *reinterpret_cast<const float4*>(wb + kk * HID + c0 + 4);
    u64 h[NPG];
    ld_grp<NPG>(h, hsrc + kk * KSTR_F);
    u64 w[8];
    w[0] = bcast2(wa.x); w[1] = bcast2(wa.y); w[2] = bcast2(wa.z); w[3] = bcast2(wa.w);
    w[4] = bcast2(wc.x); w[5] = bcast2(wc.y); w[6] = bcast2(wc.z); w[7] = bcast2(wc.w);
    #pragma unroll
    for (int p = 0; p < NPG; p++) {
      #pragma unroll
      for (int c = 0; c < 8; c++)
        acc[c][p] = ffma2(h[p], w[c], acc[c][p]);
    }
  }
}

// ------------------------------------------------------------------
// GG samples per CTA (GG in {2,4,8}); 4 row-groups always.
// ROWSG = GG*NR/4 rows per group; SPG = samples per group (GG8 -> 2).
// Virtual row vr = s*NR + i  ->  grp = vr/ROWSG, slot = vr%ROWSG.
// ------------------------------------------------------------------
template <int GG, int NR, int NSTG>
__device__ __forceinline__ void run(const Params& P, float* sm, int sbase,
                                    int send, int tid) {
  constexpr int ROWSG = GG * NR / 4;
  constexpr int SPG = (GG >= 8) ? 2 : 1;
  constexpr int GPS = (GG >= 4) ? 1 : 4 / GG;
  constexpr int NPG = ROWSG / 2;
  constexpr int GSTR_F = (((NPG * 8) + 15) & ~15) / 4;
  constexpr int KSTR_F = 4 * GSTR_F;

  float* hT   = sm;                       // HID * KSTR_F
  float* wbuf = hT + HID * KSTR_F;        // NSTG * TILE_F
  float* msgs = wbuf + NSTG * TILE_F;     // GG * HID
  float* dsm  = msgs + GG * HID;          // GG
  float* nfs  = wbuf;                     // overlay (embed phase only)
  u64*  red   = reinterpret_cast<u64*>(wbuf);  // overlay (between streams)

  const int lane = tid & 31, warp = tid >> 5;
  const int cg = tid >> 2, rg = tid & 3, c0 = cg * 8;
  const int g = (SPG == 2) ? rg * 2 : rg / GPS;
  const int rbase = (SPG == 2) ? 0 : (rg % GPS) * ROWSG;

  int sid[GG]; int ncv[GG]; float invd[GG]; bool wok[GG];
  #pragma unroll
  for (int s = 0; s < GG; s++) {
    const int ss = sbase + s;
    wok[s] = (ss < send);
    sid[s] = wok[s] ? d_perm[ss] : 0;
    int nc = wok[s] ? P.nn_c[sid[s]] : 0;
    ncv[s] = min(max(nc, 0), NOBJ);
    invd[s] = 1.0f / (float)(ncv[s] > 0 ? ncv[s] : 1);
  }
  int ncvA = 0, ncvB = 0; float invdA = 1.f, invdB = 1.f;
  #pragma unroll
  for (int s = 0; s < GG; s++) {
    if (s == g) { ncvA = ncv[s]; invdA = invd[s]; }
    if (SPG == 2 && s == g + 1) { ncvB = ncv[s]; invdB = invd[s]; }
  }

  // node features
  for (int idx = tid; idx < GG * 80; idx += NT) {
    const int s = idx / 80, o = idx % 80;
    reinterpret_cast<float4*>(nfs)[idx] =
        reinterpret_cast<const float4*>(P.nf + (size_t)sid[s] * (NOBJ * NFD))[o];
  }
  __syncthreads();

  // ---------- node embed ----------
  #pragma unroll
  for (int half = 0; half < 2; half++) {
    const int j = tid + half * NT;
    float wv[NFD];
    #pragma unroll
    for (int k = 0; k < NFD; k++) wv[k] = P.neW[k * HID + j];
    const float bias = P.neb[j];
    #pragma unroll
    for (int s = 0; s < GG; s++) {
      float ms = 0.f;
      #pragma unroll
      for (int i = 0; i < NR; i += 2) {
        float a2[2];
        #pragma unroll
        for (int t = 0; t < 2; t++) {
          const float4* rp = reinterpret_cast<const float4*>(nfs + s * 320 + (i + t) * NFD);
          float4 r0 = rp[0], r1 = rp[1], r2 = rp[2], r3 = rp[3];
          float a = bias;
          a = fmaf(r0.x, wv[0], a);  a = fmaf(r0.y, wv[1], a);
          a = fmaf(r0.z, wv[2], a);  a = fmaf(r0.w, wv[3], a);
          a = fmaf(r1.x, wv[4], a);  a = fmaf(r1.y, wv[5], a);
          a = fmaf(r1.z, wv[6], a);  a = fmaf(r1.w, wv[7], a);
          a = fmaf(r2.x, wv[8], a);  a = fmaf(r2.y, wv[9], a);
          a = fmaf(r2.z, wv[10], a); a = fmaf(r2.w, wv[11], a);
          a = fmaf(r3.x, wv[12], a); a = fmaf(r3.y, wv[13], a);
          a = fmaf(r3.z, wv[14], a); a = fmaf(r3.w, wv[15], a);
          a2[t] = a;
          if (i + t < ncv[s]) ms += a;
        }
        const int vr = s * NR + i;
        const int grp = vr / ROWSG, slot = vr % ROWSG;
        *reinterpret_cast<float2*>(hT + (size_t)j * KSTR_F + grp * GSTR_F + slot) =
            make_float2(a2[0], a2[1]);
      }
      msgs[s * HID + j] = ms * invd[s];
    }
  }
  __syncthreads();

  // ---------- two message-passing layers ----------
  #pragma unroll 1
  for (int L = 0; L < 2; L++) {
    const float* W1 = L ? P.g2W1 : P.g1W1;  const float* b1 = L ? P.g2b1 : P.g1b1;
    const float* W2 = L ? P.g2W2 : P.g1W2;  const float* b2 = L ? P.g2b2 : P.g1b2;
    const float* lg = L ? P.n2g  : P.n1g;   const float* lb = L ? P.n2b  : P.n1b;

    // ---- t = relu([h | msg] @ W1 + b1): one 64-tile stream ----
    u64 t2[8][NPG];
    float mac[SPG][8];
    #pragma unroll
    for (int sp = 0; sp < SPG; sp++)
      #pragma unroll
      for (int c = 0; c < 8; c++) mac[sp][c] = 0.f;
    #pragma unroll
    for (int c = 0; c < 8; c++)
      #pragma unroll
      for (int p = 0; p < NPG; p++) t2[c][p] = 0ull;
    stream_tiles<512 / KT, NSTG>(W1, wbuf, tid, [&](const float* wb, int k0) {
      if (k0 < HID) {
        mma_tile<NPG, KSTR_F>(wb, hT + (size_t)k0 * KSTR_F + rg * GSTR_F, c0, t2);
      } else {
        #pragma unroll 4
        for (int kk = 0; kk < KT; kk++) {
          const float4 wa = *reinterpret_cast<const float4*>(wb + kk * HID + c0);
          const float4 wc = *reinterpret_cast<const float4*>(wb + kk * HID + c0 + 4);
          const int km = k0 + kk - HID;
          #pragma unroll
          for (int sp = 0; sp < SPG; sp++) {
            const float m = msgs[(g + sp) * HID + km];
            mac[sp][0] = fmaf(m, wa.x, mac[sp][0]); mac[sp][1] = fmaf(m, wa.y, mac[sp][1]);
            mac[sp][2] = fmaf(m, wa.z, mac[sp][2]); mac[sp][3] = fmaf(m, wa.w, mac[sp][3]);
            mac[sp][4] = fmaf(m, wc.x, mac[sp][4]); mac[sp][5] = fmaf(m, wc.y, mac[sp][5]);
            mac[sp][6] = fmaf(m, wc.z, mac[sp][6]); mac[sp][7] = fmaf(m, wc.w, mac[sp][7]);
          }
        }
      }
    });

    // ---- epilogue 1: acc2 = h_old + b2 (residual pre-add); hT <- relu(t) ----
    u64 acc2[8][NPG];
    {
      const float4 b1a = *reinterpret_cast<const float4*>(b1 + c0);
      const float4 b1c = *reinterpret_cast<const float4*>(b1 + c0 + 4);
      const float4 b2a = *reinterpret_cast<const float4*>(b2 + c0);
      const float4 b2c = *reinterpret_cast<const float4*>(b2 + c0 + 4);
      const float b1v[8] = {b1a.x, b1a.y, b1a.z, b1a.w, b1c.x, b1c.y, b1c.z, b1c.w};
      const float b2v[8] = {b2a.x, b2a.y, b2a.z, b2a.w, b2c.x, b2c.y, b2c.z, b2c.w};
      #pragma unroll
      for (int c = 0; c < 8; c++) {
        float* hcol = hT + (size_t)(c0 + c) * KSTR_F + rg * GSTR_F;
        u64 hold[NPG];
        ld_grp<NPG>(hold, hcol);
        const u64 b2d = bcast2(b2v[c]);
        #pragma unroll
        for (int p = 0; p < NPG; p++) acc2[c][p] = fadd2(hold[p], b2d);
        #pragma unroll
        for (int p = 0; p < NPG; p++) {
          const int sp = (SPG == 2 && p >= NPG / 2) ? 1 : 0;
          const float m = mac[sp][c] + b1v[c];
          float2 u = unpack2(t2[c][p]);
          *reinterpret_cast<float2*>(hcol + 2 * p) =
              make_float2(fmaxf(u.x + m, 0.f), fmaxf(u.y + m, 0.f));
        }
      }
    }
    __syncthreads();

    // ---- acc2 += t @ W2 ----
    stream_tiles<HID / KT, NSTG>(W2, wbuf, tid, [&](const float* wb, int k0) {
      mma_tile<NPG, KSTR_F>(wb, hT + (size_t)k0 * KSTR_F + rg * GSTR_F, c0, acc2);
    });

    // ---- LayerNorm stats ----
    u64 s2[NPG], q2[NPG];
    #pragma unroll
    for (int p = 0; p < NPG; p++) {
      u64 s = acc2[0][p];
      u64 q = fmul2(acc2[0][p], acc2[0][p]);
      #pragma unroll
      for (int c = 1; c < 8; c++) {
        s = fadd2(s, acc2[c][p]);
        q = ffma2(acc2[c][p], acc2[c][p], q);
      }
      s2[p] = s; q2[p] = q;
    }
    #pragma unroll
    for (int off = 4; off <= 16; off <<= 1) {
      #pragma unroll
      for (int p = 0; p < NPG; p++) {
        s2[p] = fadd2(s2[p], __shfl_xor_sync(FULL_MASK, s2[p], off));
        q2[p] = fadd2(q2[p], __shfl_xor_sync(FULL_MASK, q2[p], off));
      }
    }
    if ((lane >> 2) == 0) {
      #pragma unroll
      for (int p = 0; p < NPG; p++) {
        red[((0 * 4 + warp) * 4 + rg) * NPG + p] = s2[p];
        red[((1 * 4 + warp) * 4 + rg) * NPG + p] = q2[p];
      }
    }
    __syncthreads();

    float2 mean2[NPG], rstd2[NPG];
    #pragma unroll
    for (int p = 0; p < NPG; p++) {
      u64 S = red[((0 * 4 + 0) * 4 + rg) * NPG + p];
      u64 Q = red[((1 * 4 + 0) * 4 + rg) * NPG + p];
      #pragma unroll
      for (int w = 1; w < 4; w++) {
        S = fadd2(S, red[((0 * 4 + w) * 4 + rg) * NPG + p]);
        Q = fadd2(Q, red[((1 * 4 + w) * 4 + rg) * NPG + p]);
      }
      float2 su = unpack2(S), qu = unpack2(Q);
      const float mx = su.x * (1.0f / HID), my = su.y * (1.0f / HID);
      mean2[p] = make_float2(mx, my);
      rstd2[p] = make_float2(rsqrtf(qu.x * (1.0f / HID) - mx * mx + 1e-5f),
                             rsqrtf(qu.y * (1.0f / HID) - my * my + 1e-5f));
    }

    // ---- normalize, mask, write back, new msg ----
    const float4 lga4 = *reinterpret_cast<const float4*>(lg + c0);
    const float4 lgc4 = *reinterpret_cast<const float4*>(lg + c0 + 4);
    const float4 lba4 = *reinterpret_cast<const float4*>(lb + c0);
    const float4 lbc4 = *reinterpret_cast<const float4*>(lb + c0 + 4);
    const float lgv[8] = {lga4.x, lga4.y, lga4.z, lga4.w, lgc4.x, lgc4.y, lgc4.z, lgc4.w};
    const float lbv[8] = {lba4.x, lba4.y, lba4.z, lba4.w, lbc4.x, lbc4.y, lbc4.z, lbc4.w};
    float msum[SPG][8];
    #pragma unroll
    for (int sp = 0; sp < SPG; sp++)
      #pragma unroll
      for (int c = 0; c < 8; c++) msum[sp][c] = 0.f;
    #pragma unroll
    for (int c = 0; c < 8; c++) {
      float* hcol = hT + (size_t)(c0 + c) * KSTR_F + rg * GSTR_F;
      #pragma unroll
      for (int p = 0; p < NPG; p++) {
        const int sp = (SPG == 2 && p >= NPG / 2) ? 1 : 0;
        const int nv = sp ? ncvB : ncvA;
        const int r0i = (SPG == 2) ? (2 * p) % NR : rbase + 2 * p;
        float2 u = unpack2(acc2[c][p]);
        float v0 = 0.f, v1 = 0.f;
        if (r0i     < nv) v0 = (u.x - mean2[p].x) * rstd2[p].x * lgv[c] + lbv[c];
        if (r0i + 1 < nv) v1 = (u.y - mean2[p].y) * rstd2[p].y * lgv[c] + lbv[c];
        *reinterpret_cast<float2*>(hcol + 2 * p) = make_float2(v0, v1);
        msum[sp][c] += v0 + v1;
      }
    }
    if constexpr (GPS == 2) {
      #pragma unroll
      for (int c = 0; c < 8; c++)
        msum[0][c] += __shfl_xor_sync(FULL_MASK, msum[0][c], 1);
      if ((rg & 1) == 0) {
        *reinterpret_cast<float4*>(msgs + g * HID + c0) =
            make_float4(msum[0][0] * invdA, msum[0][1] * invdA,
                        msum[0][2] * invdA, msum[0][3] * invdA);
        *reinterpret_cast<float4*>(msgs + g * HID + c0 + 4) =
            make_float4(msum[0][4] * invdA, msum[0][5] * invdA,
                        msum[0][6] * invdA, msum[0][7] * invdA);
      }
    } else {
      *reinterpret_cast<float4*>(msgs + g * HID + c0) =
          make_float4(msum[0][0] * invdA, msum[0][1] * invdA,
                      msum[0][2] * invdA, msum[0][3] * invdA);
      *reinterpret_cast<float4*>(msgs + g * HID + c0 + 4) =
          make_float4(msum[0][4] * invdA, msum[0][5] * invdA,
                      msum[0][6] * invdA, msum[0][7] * invdA);
      if constexpr (SPG == 2) {
        *reinterpret_cast<float4*>(msgs + (g + 1) * HID + c0) =
            make_float4(msum[1][0] * invdB, msum[1][1] * invdB,
                        msum[1][2] * invdB, msum[1][3] * invdB);
        *reinterpret_cast<float4*>(msgs + (g + 1) * HID + c0 + 4) =
            make_float4(msum[1][4] * invdB, msum[1][5] * invdB,
                        msum[1][6] * invdB, msum[1][7] * invdB);
      }
    }
    __syncthreads();
  }
  // msgs == per-sample g vector, hT == final h

  // ---------- dsm[s] = g·v2 + c ----------
  if (tid < GG) {
    const float* mg = msgs + tid * HID;
    float a0 = 0.f, a1 = 0.f, a2 = 0.f, a3 = 0.f;
    #pragma unroll 2
    for (int a = 0; a < HID; a += 4) {
      a0 = fmaf(mg[a + 0], d_v2[a + 0], a0);
      a1 = fmaf(mg[a + 1], d_v2[a + 1], a1);
      a2 = fmaf(mg[a + 2], d_v2[a + 2], a2);
      a3 = fmaf(mg[a + 3], d_v2[a + 3], a3);
    }
    dsm[tid] = d_c + (a0 + a1) + (a2 + a3);
  }

  // ---------- w[sp] = g_sp @ M + v1 (streamed) ----------
  float wv[SPG][8];
  {
    const float4 va = *reinterpret_cast<const float4*>(d_v1 + c0);
    const float4 vc = *reinterpret_cast<const float4*>(d_v1 + c0 + 4);
    #pragma unroll
    for (int sp = 0; sp < SPG; sp++) {
      wv[sp][0] = va.x; wv[sp][1] = va.y; wv[sp][2] = va.z; wv[sp][3] = va.w;
      wv[sp][4] = vc.x; wv[sp][5] = vc.y; wv[sp][6] = vc.z; wv[sp][7] = vc.w;
    }
  }
  stream_tiles<HID / KT, NSTG>(d_M, wbuf, tid, [&](const float* wb, int k0) {
    #pragma unroll 4
    for (int kk = 0; kk < KT; kk++) {
      const float4 wa = *reinterpret_cast<const float4*>(wb + kk * HID + c0);
      const float4 wc = *reinterpret_cast<const float4*>(wb + kk * HID + c0 + 4);
      #pragma unroll
      for (int sp = 0; sp < SPG; sp++) {
        const float m = msgs[(g + sp) * HID + k0 + kk];
        wv[sp][0] = fmaf(m, wa.x, wv[sp][0]); wv[sp][1] = fmaf(m, wa.y, wv[sp][1]);
        wv[sp][2] = fmaf(m, wa.z, wv[sp][2]); wv[sp][3] = fmaf(m, wa.w, wv[sp][3]);
        wv[sp][4] = fmaf(m, wc.x, wv[sp][4]); wv[sp][5] = fmaf(m, wc.y, wv[sp][5]);
        wv[sp][6] = fmaf(m, wc.z, wv[sp][6]); wv[sp][7] = fmaf(m, wc.w, wv[sp][7]);
      }
    }
  });

  // ---------- pl partials ----------
  {
    u64 part[NPG];
    #pragma unroll
    for (int p = 0; p < NPG; p++) part[p] = 0ull;
    #pragma unroll
    for (int c = 0; c < 8; c++) {
      u64 h[NPG];
      ld_grp<NPG>(h, hT + (size_t)(c0 + c) * KSTR_F + rg * GSTR_F);
      #pragma unroll
      for (int p = 0; p < NPG; p++) {
        const int sp = (SPG == 2 && p >= NPG / 2) ? 1 : 0;
        part[p] = ffma2(h[p], bcast2(wv[sp][c]), part[p]);
      }
    }
    #pragma unroll
    for (int off = 4; off <= 16; off <<= 1)
      #pragma unroll
      for (int p = 0; p < NPG; p++)
        part[p] = fadd2(part[p], __shfl_xor_sync(FULL_MASK, part[p], off));
    if ((lane >> 2) == 0) {
      #pragma unroll
      for (int p = 0; p < NPG; p++)
        red[((0 * 4 + warp) * 4 + rg) * NPG + p] = part[p];
    }
  }
  __syncthreads();

  // ---------- pl output (all 20 slots; masked -> -1e9) ----------
  for (int idx = tid; idx < GG * NOBJ; idx += NT) {
    const int s = idx / NOBJ, i = idx % NOBJ;
    if (wok[s]) {
      float v = -1e9f;
      if (i < ncv[s]) {
        const int vr = s * NR + i;
        const int grp = vr / ROWSG, slot = vr % ROWSG;
        const int p = slot >> 1, hh = slot & 1;
        u64 S = red[((0 * 4 + 0) * 4 + grp) * NPG + p];
        #pragma unroll
        for (int w = 1; w < 4; w++)
          S = fadd2(S, red[((0 * 4 + w) * 4 + grp) * NPG + p]);
        float2 u = unpack2(S);
        v = (hh ? u.y : u.x) + dsm[s];
      }
      P.out[(size_t)P.B * 28 + (size_t)sid[s] * NOBJ + i] = v;
    }
  }

  // ---------- small heads from g-vector ----------
  for (int idx = tid; idx < GG * 28; idx += NT) {
    const int s = idx / 28;
    int cc = idx % 28;
    if (wok[s]) {
      const float* W; float bb; float* o; int no;
      if (cc < 8)       { W = P.ohW;  bb = P.ohb[cc];      no = 8;
                          o = P.out + (size_t)sid[s] * 8 + cc; }
      else if (cc < 18) { cc -= 8;  W = P.c1W; bb = P.c1b[cc]; no = 10;
                          o = P.out + (size_t)P.B * 8 + (size_t)sid[s] * 10 + cc; }
      else              { cc -= 18; W = P.c2W; bb = P.c2b[cc]; no = 10;
                          o = P.out + (size_t)P.B * 18 + (size_t)sid[s] * 10 + cc; }
      float a0 = bb, a1 = 0.f, a2 = 0.f, a3 = 0.f;
      const float* mg = msgs + s * HID;
      #pragma unroll 2
      for (int k = 0; k < HID; k += 4) {
        a0 = fmaf(mg[k + 0], W[(k + 0) * no + cc], a0);
        a1 = fmaf(mg[k + 1], W[(k + 1) * no + cc], a1);
        a2 = fmaf(mg[k + 2], W[(k + 2) * no + cc], a2);
        a3 = fmaf(mg[k + 3], W[(k + 3) * no + cc], a3);
      }
      *o = (a0 + a1) + (a2 + a3);
    }
  }
}

// ---------------- prep kernels ----------------
__global__ void tr_kernel(const float* __restrict__ pkW) {
  const int t = blockIdx.x, b = threadIdx.x;
  d_pkWT[t * HID + b] = pkW[b * HID + t];
  if (t == 0 && b < NBUCK) { d_bcnt[b] = 0; d_ticket[b] = 0; }
}

__global__ void m_kernel(const float* __restrict__ pqW) {
  __shared__ float spq[HID];
  const int a = blockIdx.x, b = threadIdx.x;
  spq[b] = pqW[a * HID + b];
  __syncthreads();
  float s0 = 0.f, s1 = 0.f, s2 = 0.f, s3 = 0.f;
  #pragma unroll 4
  for (int t = 0; t < HID; t += 4) {
    s0 = fmaf(spq[t + 0], d_pkWT[(t + 0) * HID + b], s0);
    s1 = fmaf(spq[t + 1], d_pkWT[(t + 1) * HID + b], s1);
    s2 = fmaf(spq[t + 2], d_pkWT[(t + 2) * HID + b], s2);
    s3 = fmaf(spq[t + 3], d_pkWT[(t + 3) * HID + b], s3);
  }
  d_M[a * HID + b] = (s0 + s1) + (s2 + s3);
}

__global__ void vec_kernel(const float* __restrict__ pqW,
                           const float* __restrict__ pqb,
                           const float* __restrict__ pkb) {
  const int tid = threadIdx.x;
  if (tid < HID) {
    float a = 0.f;
    for (int t = 0; t < HID; t++)
      a = fmaf(pqb[t], d_pkWT[t * HID + tid], a);
    d_v1[tid] = a;
    if (tid == 0) {
      float cc = 0.f;
      for (int t = 0; t < HID; t++) cc = fmaf(pqb[t], pkb[t], cc);
      d_c = cc;
    }
  } else {
    const int a = tid - HID;
    float s = 0.f;
    for (int t = 0; t < HID; t++)
      s = fmaf(pqW[a * HID + t], pkb[t], s);
    d_v2[a] = s;
  }
}

// ---- chip-parallel pack: histogram -> bases -> ticketed scatter ----
// (slot order within a bucket is nondeterministic, but every sample's math
//  and output location depend only on its own sid, so d_out is identical)
__global__ void cnt_kernel(const int* __restrict__ nn_c, int B) {
  const int i = blockIdx.x * blockDim.x + threadIdx.x;
  if (i < B)
    atomicAdd(&d_bcnt[bucket_of(min(max(nn_c[i], 0), NOBJ))], 1);
}

__global__ void base_kernel() {
  int cb = 0, sb = 0;
  for (int b = 0; b < NBUCK; b++) {
    d_cta_base[b] = cb;
    d_slot_base[b] = sb;
    const int gg = gg_of(b);
    cb += (d_bcnt[b] + gg - 1) / gg;
    sb += d_bcnt[b];
  }
  d_cta_base[NBUCK] = cb;
  d_slot_base[NBUCK] = sb;
}

__global__ void scat_kernel(const int* __restrict__ nn_c, int B) {
  const int i = blockIdx.x * blockDim.x + threadIdx.x;
  if (i < B) {
    const int b = bucket_of(min(max(nn_c[i], 0), NOBJ));
    const int slot = d_slot_base[b] + atomicAdd(&d_ticket[b], 1);
    d_perm[slot] = i;
  }
}

__global__ void __launch_bounds__(NT, 3) gnn_kernel(Params P) {
  extern __shared__ __align__(16) float sm[];
  const int c = blockIdx.x;
  if (c >= d_cta_base[NBUCK]) return;
  int b = 0;
  #pragma unroll
  for (int i = 1; i < NBUCK; i++)
    if (c >= d_cta_base[i]) b = i;
  const int gg = gg_of(b);
  const int sbase = d_slot_base[b] + (c - d_cta_base[b]) * gg;
  const int send = d_slot_base[b + 1];
  const int tid = threadIdx.x;
  switch (b) {
    case 0:  run<8, 4, 3>(P, sm, sbase, send, tid);  break;
    case 1:  run<4, 8, 3>(P, sm, sbase, send, tid);  break;
    case 2:  run<4, 10, 2>(P, sm, sbase, send, tid); break;
    case 3:  run<2, 12, 3>(P, sm, sbase, send, tid); break;
    case 4:  run<2, 16, 3>(P, sm, sbase, send, tid); break;
    default: run<2, 20, 3>(P, sm, sbase, send, tid); break;
  }
}

// smem = max over variants: HID*KSTR_F + NSTG*TILE_F + GG*HID + GG(dsm)
//   GG2,NR20,3st: 256*48 + 3*2048 + 512 + 16 = 18960 floats (75,840 B) <- max
constexpr int SMEM_BYTES = 18960 * 4;  // 3 CTAs/SM

}  // namespace

extern "C" void kernel_launch(void* const* d_in, const int* in_sizes, int n_in,
                              void* d_out, int out_size) {
  Params P;
  P.nf   = (const float*)d_in[0];
  P.nn_c = (const int*)d_in[1];
  P.neW  = (const float*)d_in[2];  P.neb  = (const float*)d_in[3];
  P.g1W1 = (const float*)d_in[4];  P.g1b1 = (const float*)d_in[5];
  P.g1W2 = (const float*)d_in[6];  P.g1b2 = (const float*)d_in[7];
  P.g2W1 = (const float*)d_in[8];  P.g2b1 = (const float*)d_in[9];
  P.g2W2 = (const float*)d_in[10]; P.g2b2 = (const float*)d_in[11];
  P.n1g  = (const float*)d_in[12]; P.n1b  = (const float*)d_in[13];
  P.n2g  = (const float*)d_in[14]; P.n2b  = (const float*)d_in[15];
  P.ohW  = (const float*)d_in[16]; P.ohb  = (const float*)d_in[17];
  P.c1W  = (const float*)d_in[18]; P.c1b  = (const float*)d_in[19];
  P.c2W  = (const float*)d_in[20]; P.c2b  = (const float*)d_in[21];
  P.pqW  = (const float*)d_in[22]; P.pqb  = (const float*)d_in[23];
  P.pkW  = (const float*)d_in[24]; P.pkb  = (const float*)d_in[25];
  P.out  = (float*)d_out;
  P.B    = in_sizes[1];

  cudaFuncSetAttribute(gnn_kernel, cudaFuncAttributeMaxDynamicSharedMemorySize,
                       SMEM_BYTES);

  tr_kernel<<<HID, HID>>>(P.pkW);   // also zeroes d_bcnt / d_ticket
  m_kernel<<<HID, HID>>>(P.pqW);
  vec_kernel<<<1, 512>>>(P.pqW, P.pqb, P.pkb);
  const int pblk = (P.B + 255) / 256;
  cnt_kernel<<<pblk, 256>>>(P.nn_c, P.B);
  base_kernel<<<1, 1>>>();
  scat_kernel<<<pblk, 256>>>(P.nn_c, P.B);
  const int nblocks = (P.B + 1) / 2;
  gnn_kernel<<<nblocks, NT, SMEM_BYTES>>>(P);
}